// round 1
// baseline (speedup 1.0000x reference)
#include <cuda_runtime.h>
#include <math.h>
#include <stdint.h>

#define BATCH 2
#define SEQ   2048
#define DIMM  4096
#define NH    32
#define NKV   8
#define HD    128
#define MROWS (BATCH * SEQ)   // 4096

// ---------------- scratch (static device globals; no allocation) -------------
__device__ float g_q[(size_t)MROWS * DIMM];            // 64 MB  [B,S,H,hd]
__device__ float g_k[(size_t)MROWS * NKV * HD];        // 16 MB  [B,S,KV,hd]
__device__ float g_v[(size_t)MROWS * NKV * HD];        // 16 MB
__device__ float g_attn[(size_t)MROWS * DIMM];         // 64 MB  [B,S,H,hd]

// ---------------- GEMM: C[M,N] = A[M,K] @ B[N,K]^T  (both K-major) -----------
__global__ __launch_bounds__(256) void sgemm_nt(const float* __restrict__ A,
                                                const float* __restrict__ B,
                                                float* __restrict__ C,
                                                int M, int N, int K) {
    __shared__ float As[16][128];
    __shared__ float Bs[16][128];
    const int tid = threadIdx.x;
    const int bm = blockIdx.y * 128;
    const int bn = blockIdx.x * 128;
    const int tm = (tid >> 4) << 3;
    const int tn = (tid & 15) << 3;

    float acc[8][8];
#pragma unroll
    for (int i = 0; i < 8; i++)
#pragma unroll
        for (int j = 0; j < 8; j++) acc[i][j] = 0.f;

    for (int k0 = 0; k0 < K; k0 += 16) {
#pragma unroll
        for (int it = 0; it < 2; it++) {
            int lin = tid + it * 256;
            int row = lin >> 2;
            int c4  = (lin & 3) << 2;
            float4 va = *reinterpret_cast<const float4*>(&A[(size_t)(bm + row) * K + k0 + c4]);
            As[c4 + 0][row] = va.x; As[c4 + 1][row] = va.y;
            As[c4 + 2][row] = va.z; As[c4 + 3][row] = va.w;
            float4 vb = *reinterpret_cast<const float4*>(&B[(size_t)(bn + row) * K + k0 + c4]);
            Bs[c4 + 0][row] = vb.x; Bs[c4 + 1][row] = vb.y;
            Bs[c4 + 2][row] = vb.z; Bs[c4 + 3][row] = vb.w;
        }
        __syncthreads();
#pragma unroll
        for (int kk = 0; kk < 16; kk++) {
            float a[8], b[8];
            *reinterpret_cast<float4*>(a)     = *reinterpret_cast<const float4*>(&As[kk][tm]);
            *reinterpret_cast<float4*>(a + 4) = *reinterpret_cast<const float4*>(&As[kk][tm + 4]);
            *reinterpret_cast<float4*>(b)     = *reinterpret_cast<const float4*>(&Bs[kk][tn]);
            *reinterpret_cast<float4*>(b + 4) = *reinterpret_cast<const float4*>(&Bs[kk][tn + 4]);
#pragma unroll
            for (int i = 0; i < 8; i++)
#pragma unroll
                for (int j = 0; j < 8; j++)
                    acc[i][j] = fmaf(a[i], b[j], acc[i][j]);
        }
        __syncthreads();
    }
#pragma unroll
    for (int i = 0; i < 8; i++) {
#pragma unroll
        for (int j4 = 0; j4 < 2; j4++) {
            float4 v = make_float4(acc[i][j4 * 4 + 0], acc[i][j4 * 4 + 1],
                                   acc[i][j4 * 4 + 2], acc[i][j4 * 4 + 3]);
            *reinterpret_cast<float4*>(&C[(size_t)(bm + tm + i) * N + bn + tn + j4 * 4]) = v;
        }
    }
}

// ---------------- RoPE (interleaved pairs, pos = s within sequence) ----------
__global__ void rope_kernel(float* __restrict__ t, const float* __restrict__ fc,
                            const float* __restrict__ fs, int nheads, int total) {
    int idx = blockIdx.x * blockDim.x + threadIdx.x;
    if (idx >= total) return;
    int i = idx & 63;                          // pair index within head
    int s = (idx / (64 * nheads)) & (SEQ - 1); // sequence position
    float c  = fc[s * 64 + i];
    float sn = fs[s * 64 + i];
    float2* p = reinterpret_cast<float2*>(t);
    float2 v = p[idx];
    p[idx] = make_float2(v.x * c - v.y * sn, v.x * sn + v.y * c);
}

// ---------------- causal flash attention (fp32, GQA 4:1) ---------------------
#define FB 64            // Br = Bc = 64
#define LT 132           // padded tile row stride (floats)
#define LS 68            // padded score row stride
#define FA_SMEM ((4 * FB * LT + FB * LS + 3 * FB + 4 * FB) * 4)

__global__ __launch_bounds__(256) void flash_kernel(const float* __restrict__ q,
                                                    const float* __restrict__ k,
                                                    const float* __restrict__ v,
                                                    float* __restrict__ o) {
    extern __shared__ float smf[];
    float* Qs = smf;
    float* Ks = Qs + FB * LT;
    float* Vs = Ks + FB * LT;
    float* Os = Vs + FB * LT;
    float* Ss = Os + FB * LT;
    float* mrow = Ss + FB * LS;
    float* lrow = mrow + FB;
    float* arow = lrow + FB;
    float* red  = arow + FB;   // [row*4 + quarter]

    const int tid = threadIdx.x;
    const int qt  = gridDim.x - 1 - blockIdx.x;  // heavy (later) tiles first
    const int h   = blockIdx.y;
    const int b   = blockIdx.z;
    const int kvh = h >> 2;                       // N_REP = 4

    // load Q tile [64 x 128]
    for (int i = tid; i < FB * 32; i += 256) {
        int r  = i >> 5;
        int d4 = (i & 31) << 2;
        int s  = qt * FB + r;
        float4 val = *reinterpret_cast<const float4*>(
            &q[(((size_t)b * SEQ + s) * NH + h) * HD + d4]);
        *reinterpret_cast<float4*>(&Qs[r * LT + d4]) = val;
    }
    for (int i = tid; i < FB * LT; i += 256) Os[i] = 0.f;
    if (tid < FB) { mrow[tid] = -INFINITY; lrow[tid] = 0.f; }
    __syncthreads();

    const int tx = tid & 15, ty = tid >> 4;
    const int row = tid & 63, quarter = tid >> 6;
    const float sc = 0.08838834764831845f;   // 1/sqrt(128)

    for (int kt = 0; kt <= qt; kt++) {
        // load K, V tiles
        for (int i = tid; i < FB * 32; i += 256) {
            int r  = i >> 5;
            int d4 = (i & 31) << 2;
            int s  = kt * FB + r;
            size_t base = (((size_t)b * SEQ + s) * NKV + kvh) * HD + d4;
            *reinterpret_cast<float4*>(&Ks[r * LT + d4]) =
                *reinterpret_cast<const float4*>(&k[base]);
            *reinterpret_cast<float4*>(&Vs[r * LT + d4]) =
                *reinterpret_cast<const float4*>(&v[base]);
        }
        __syncthreads();

        // S = Q K^T  (64x64, each thread 4x4)
        float acc[4][4];
#pragma unroll
        for (int i = 0; i < 4; i++)
#pragma unroll
            for (int j = 0; j < 4; j++) acc[i][j] = 0.f;

        for (int kk = 0; kk < HD; kk += 4) {
            float4 qv[4], kv4[4];
#pragma unroll
            for (int i = 0; i < 4; i++)
                qv[i] = *reinterpret_cast<const float4*>(&Qs[(ty * 4 + i) * LT + kk]);
#pragma unroll
            for (int j = 0; j < 4; j++)
                kv4[j] = *reinterpret_cast<const float4*>(&Ks[(tx * 4 + j) * LT + kk]);
#pragma unroll
            for (int i = 0; i < 4; i++)
#pragma unroll
                for (int j = 0; j < 4; j++)
                    acc[i][j] += qv[i].x * kv4[j].x + qv[i].y * kv4[j].y +
                                 qv[i].z * kv4[j].z + qv[i].w * kv4[j].w;
        }
#pragma unroll
        for (int i = 0; i < 4; i++)
#pragma unroll
            for (int j = 0; j < 4; j++) {
                int r = ty * 4 + i, c = tx * 4 + j;
                float sv = acc[i][j] * sc;
                if (kt == qt && c > r) sv = -INFINITY;
                Ss[r * LS + c] = sv;
            }
        __syncthreads();

        // online softmax: partial row max
        float pm = -INFINITY;
#pragma unroll
        for (int c = 0; c < 16; c++)
            pm = fmaxf(pm, Ss[row * LS + quarter * 16 + c]);
        red[row * 4 + quarter] = pm;
        __syncthreads();
        if (tid < FB) {
            float mo = mrow[tid];
            float mn = fmaxf(fmaxf(red[tid * 4 + 0], red[tid * 4 + 1]),
                             fmaxf(red[tid * 4 + 2], red[tid * 4 + 3]));
            mn = fmaxf(mo, mn);
            mrow[tid] = mn;
            arow[tid] = __expf(mo - mn);
        }
        __syncthreads();

        // exponentiate + partial sums
        float mn = mrow[row];
        float psum = 0.f;
#pragma unroll
        for (int c = 0; c < 16; c++) {
            float e = __expf(Ss[row * LS + quarter * 16 + c] - mn);
            Ss[row * LS + quarter * 16 + c] = e;
            psum += e;
        }
        red[row * 4 + quarter] = psum;
        __syncthreads();
        if (tid < FB)
            lrow[tid] = lrow[tid] * arow[tid] +
                        red[tid * 4 + 0] + red[tid * 4 + 1] +
                        red[tid * 4 + 2] + red[tid * 4 + 3];

        // O = O*alpha + P @ V   (each thread 4 rows x 8 cols)
        float oacc[4][8];
#pragma unroll
        for (int i = 0; i < 4; i++) {
            float al = arow[ty * 4 + i];
            float4 o0 = *reinterpret_cast<const float4*>(&Os[(ty * 4 + i) * LT + tx * 8]);
            float4 o1 = *reinterpret_cast<const float4*>(&Os[(ty * 4 + i) * LT + tx * 8 + 4]);
            oacc[i][0] = o0.x * al; oacc[i][1] = o0.y * al;
            oacc[i][2] = o0.z * al; oacc[i][3] = o0.w * al;
            oacc[i][4] = o1.x * al; oacc[i][5] = o1.y * al;
            oacc[i][6] = o1.z * al; oacc[i][7] = o1.w * al;
        }
        for (int kk = 0; kk < FB; kk++) {
            float4 v0 = *reinterpret_cast<const float4*>(&Vs[kk * LT + tx * 8]);
            float4 v1 = *reinterpret_cast<const float4*>(&Vs[kk * LT + tx * 8 + 4]);
#pragma unroll
            for (int i = 0; i < 4; i++) {
                float p = Ss[(ty * 4 + i) * LS + kk];
                oacc[i][0] = fmaf(p, v0.x, oacc[i][0]);
                oacc[i][1] = fmaf(p, v0.y, oacc[i][1]);
                oacc[i][2] = fmaf(p, v0.z, oacc[i][2]);
                oacc[i][3] = fmaf(p, v0.w, oacc[i][3]);
                oacc[i][4] = fmaf(p, v1.x, oacc[i][4]);
                oacc[i][5] = fmaf(p, v1.y, oacc[i][5]);
                oacc[i][6] = fmaf(p, v1.z, oacc[i][6]);
                oacc[i][7] = fmaf(p, v1.w, oacc[i][7]);
            }
        }
#pragma unroll
        for (int i = 0; i < 4; i++) {
            *reinterpret_cast<float4*>(&Os[(ty * 4 + i) * LT + tx * 8]) =
                make_float4(oacc[i][0], oacc[i][1], oacc[i][2], oacc[i][3]);
            *reinterpret_cast<float4*>(&Os[(ty * 4 + i) * LT + tx * 8 + 4]) =
                make_float4(oacc[i][4], oacc[i][5], oacc[i][6], oacc[i][7]);
        }
        __syncthreads();
    }

    // epilogue: O /= l, write to attn buffer [B,S,H,hd]
    for (int i = tid; i < FB * 32; i += 256) {
        int r  = i >> 5;
        int d4 = (i & 31) << 2;
        float inv = 1.f / lrow[r];
        float4 ov = *reinterpret_cast<const float4*>(&Os[r * LT + d4]);
        ov.x *= inv; ov.y *= inv; ov.z *= inv; ov.w *= inv;
        int s = qt * FB + r;
        *reinterpret_cast<float4*>(
            &o[(((size_t)b * SEQ + s) * NH + h) * HD + d4]) = ov;
    }
}

// ---------------- launch ------------------------------------------------------
extern "C" void kernel_launch(void* const* d_in, const int* in_sizes, int n_in,
                              void* d_out, int out_size) {
    const float* x  = (const float*)d_in[0];
    const float* wq = (const float*)d_in[1];
    const float* wk = (const float*)d_in[2];
    const float* wv = (const float*)d_in[3];
    const float* wo = (const float*)d_in[4];
    const float* fc = (const float*)d_in[5];
    const float* fs = (const float*)d_in[6];
    float* out = (float*)d_out;

    float *qp, *kp, *vp, *ap;
    cudaGetSymbolAddress((void**)&qp, g_q);
    cudaGetSymbolAddress((void**)&kp, g_k);
    cudaGetSymbolAddress((void**)&vp, g_v);
    cudaGetSymbolAddress((void**)&ap, g_attn);

    cudaFuncSetAttribute(flash_kernel, cudaFuncAttributeMaxDynamicSharedMemorySize,
                         FA_SMEM);

    // projections: out[M,N] = x[M,K] @ W[N,K]^T
    sgemm_nt<<<dim3(DIMM / 128, MROWS / 128), 256>>>(x, wq, qp, MROWS, DIMM, DIMM);
    sgemm_nt<<<dim3((NKV * HD) / 128, MROWS / 128), 256>>>(x, wk, kp, MROWS, NKV * HD, DIMM);
    sgemm_nt<<<dim3((NKV * HD) / 128, MROWS / 128), 256>>>(x, wv, vp, MROWS, NKV * HD, DIMM);

    // RoPE
    {
        int totq = BATCH * SEQ * NH * (HD / 2);
        int totk = BATCH * SEQ * NKV * (HD / 2);
        rope_kernel<<<(totq + 255) / 256, 256>>>(qp, fc, fs, NH, totq);
        rope_kernel<<<(totk + 255) / 256, 256>>>(kp, fc, fs, NKV, totk);
    }

    // causal flash attention
    flash_kernel<<<dim3(SEQ / FB, NH, BATCH), 256, FA_SMEM>>>(qp, kp, vp, ap);

    // output projection
    sgemm_nt<<<dim3(DIMM / 128, MROWS / 128), 256>>>(ap, wo, out, MROWS, DIMM, DIMM);
}

// round 2
// speedup vs baseline: 1.8235x; 1.8235x over previous
#include <cuda_runtime.h>
#include <math.h>
#include <stdint.h>

#define BATCH 2
#define SEQ   2048
#define DIMM  4096
#define NH    32
#define NKV   8
#define HD    128
#define MROWS (BATCH * SEQ)   // 4096

// ---------------- scratch (static device globals; no allocation) -------------
__device__ float g_q[(size_t)MROWS * DIMM];            // 64 MB  [B,S,H,hd]
__device__ float g_k[(size_t)MROWS * NKV * HD];        // 16 MB  [B,S,KV,hd]
__device__ float g_v[(size_t)MROWS * NKV * HD];        // 16 MB
__device__ float g_attn[(size_t)MROWS * DIMM];         // 64 MB  [B,S,H,hd]

// ============================================================================
// tf32 tensor-core GEMM: C[M,N] = A[M,K] @ B[N,K]^T
// CTA tile 128x128x16, 8 warps (2x4), warp tile 64x32, mma.sync.m16n8k8.tf32
// ============================================================================
#define BM 128
#define BN 128
#define BK 16
#define SAST 20   // padded row stride (floats) for [row][k] tiles

__device__ __forceinline__ uint32_t f2tf32(float x) {
    uint32_t u;
    asm("cvt.rna.tf32.f32 %0, %1;" : "=r"(u) : "f"(x));
    return u;
}

__global__ __launch_bounds__(256, 2) void tf32_gemm_nt(const float* __restrict__ A,
                                                       const float* __restrict__ B,
                                                       float* __restrict__ C,
                                                       int M, int N, int K) {
    __shared__ float As[2][BM * SAST];
    __shared__ float Bs[2][BN * SAST];

    const int tid  = threadIdx.x;
    const int lane = tid & 31;
    const int wid  = tid >> 5;
    const int bm = blockIdx.y * BM;
    const int bn = blockIdx.x * BN;
    const int warp_m = (wid & 1) * 64;
    const int warp_n = (wid >> 1) * 32;

    // per-thread staging coords: two float4 rows per matrix tile
    const int r0 = tid >> 2;                 // 0..63
    const int c0 = (tid & 3) << 2;           // 0,4,8,12
    const int r1 = r0 + 64;

    const float* Ag0 = A + (size_t)(bm + r0) * K + c0;
    const float* Ag1 = A + (size_t)(bm + r1) * K + c0;
    const float* Bg0 = B + (size_t)(bn + r0) * K + c0;
    const float* Bg1 = B + (size_t)(bn + r1) * K + c0;

    float acc[4][4][4];   // [mt][nt][c0..c3]
#pragma unroll
    for (int i = 0; i < 4; i++)
#pragma unroll
        for (int j = 0; j < 4; j++)
#pragma unroll
            for (int c = 0; c < 4; c++) acc[i][j][c] = 0.f;

    // prologue: tile 0 -> smem buf 0
    {
        float4 va0 = *reinterpret_cast<const float4*>(Ag0);
        float4 va1 = *reinterpret_cast<const float4*>(Ag1);
        float4 vb0 = *reinterpret_cast<const float4*>(Bg0);
        float4 vb1 = *reinterpret_cast<const float4*>(Bg1);
        uint32_t* pa0 = reinterpret_cast<uint32_t*>(&As[0][r0 * SAST + c0]);
        uint32_t* pa1 = reinterpret_cast<uint32_t*>(&As[0][r1 * SAST + c0]);
        uint32_t* pb0 = reinterpret_cast<uint32_t*>(&Bs[0][r0 * SAST + c0]);
        uint32_t* pb1 = reinterpret_cast<uint32_t*>(&Bs[0][r1 * SAST + c0]);
        pa0[0]=f2tf32(va0.x); pa0[1]=f2tf32(va0.y); pa0[2]=f2tf32(va0.z); pa0[3]=f2tf32(va0.w);
        pa1[0]=f2tf32(va1.x); pa1[1]=f2tf32(va1.y); pa1[2]=f2tf32(va1.z); pa1[3]=f2tf32(va1.w);
        pb0[0]=f2tf32(vb0.x); pb0[1]=f2tf32(vb0.y); pb0[2]=f2tf32(vb0.z); pb0[3]=f2tf32(vb0.w);
        pb1[0]=f2tf32(vb1.x); pb1[1]=f2tf32(vb1.y); pb1[2]=f2tf32(vb1.z); pb1[3]=f2tf32(vb1.w);
    }
    __syncthreads();

    int buf = 0;
    for (int k0 = 0; k0 < K; k0 += BK) {
        // prefetch next tile into registers
        float4 va0, va1, vb0, vb1;
        const bool more = (k0 + BK) < K;
        if (more) {
            va0 = *reinterpret_cast<const float4*>(Ag0 + k0 + BK);
            va1 = *reinterpret_cast<const float4*>(Ag1 + k0 + BK);
            vb0 = *reinterpret_cast<const float4*>(Bg0 + k0 + BK);
            vb1 = *reinterpret_cast<const float4*>(Bg1 + k0 + BK);
        }

        const float* sA = &As[buf][0];
        const float* sB = &Bs[buf][0];
#pragma unroll
        for (int kk = 0; kk < BK; kk += 8) {
            uint32_t afr[4][4];
            uint32_t bfr[4][2];
#pragma unroll
            for (int mt = 0; mt < 4; mt++) {
                const int mrow = warp_m + mt * 16 + (lane >> 2);
                const int kc   = kk + (lane & 3);
                afr[mt][0] = reinterpret_cast<const uint32_t*>(sA)[mrow * SAST + kc];
                afr[mt][1] = reinterpret_cast<const uint32_t*>(sA)[(mrow + 8) * SAST + kc];
                afr[mt][2] = reinterpret_cast<const uint32_t*>(sA)[mrow * SAST + kc + 4];
                afr[mt][3] = reinterpret_cast<const uint32_t*>(sA)[(mrow + 8) * SAST + kc + 4];
            }
#pragma unroll
            for (int nt = 0; nt < 4; nt++) {
                const int nrow = warp_n + nt * 8 + (lane >> 2);
                const int kc   = kk + (lane & 3);
                bfr[nt][0] = reinterpret_cast<const uint32_t*>(sB)[nrow * SAST + kc];
                bfr[nt][1] = reinterpret_cast<const uint32_t*>(sB)[nrow * SAST + kc + 4];
            }
#pragma unroll
            for (int mt = 0; mt < 4; mt++)
#pragma unroll
                for (int nt = 0; nt < 4; nt++) {
                    asm volatile(
                        "mma.sync.aligned.m16n8k8.row.col.f32.tf32.tf32.f32 "
                        "{%0,%1,%2,%3},{%4,%5,%6,%7},{%8,%9},{%0,%1,%2,%3};"
                        : "+f"(acc[mt][nt][0]), "+f"(acc[mt][nt][1]),
                          "+f"(acc[mt][nt][2]), "+f"(acc[mt][nt][3])
                        : "r"(afr[mt][0]), "r"(afr[mt][1]),
                          "r"(afr[mt][2]), "r"(afr[mt][3]),
                          "r"(bfr[nt][0]), "r"(bfr[nt][1]));
                }
        }

        if (more) {
            const int nb = buf ^ 1;
            uint32_t* pa0 = reinterpret_cast<uint32_t*>(&As[nb][r0 * SAST + c0]);
            uint32_t* pa1 = reinterpret_cast<uint32_t*>(&As[nb][r1 * SAST + c0]);
            uint32_t* pb0 = reinterpret_cast<uint32_t*>(&Bs[nb][r0 * SAST + c0]);
            uint32_t* pb1 = reinterpret_cast<uint32_t*>(&Bs[nb][r1 * SAST + c0]);
            pa0[0]=f2tf32(va0.x); pa0[1]=f2tf32(va0.y); pa0[2]=f2tf32(va0.z); pa0[3]=f2tf32(va0.w);
            pa1[0]=f2tf32(va1.x); pa1[1]=f2tf32(va1.y); pa1[2]=f2tf32(va1.z); pa1[3]=f2tf32(va1.w);
            pb0[0]=f2tf32(vb0.x); pb0[1]=f2tf32(vb0.y); pb0[2]=f2tf32(vb0.z); pb0[3]=f2tf32(vb0.w);
            pb1[0]=f2tf32(vb1.x); pb1[1]=f2tf32(vb1.y); pb1[2]=f2tf32(vb1.z); pb1[3]=f2tf32(vb1.w);
            __syncthreads();
            buf = nb;
        }
    }

    // epilogue
#pragma unroll
    for (int mt = 0; mt < 4; mt++) {
#pragma unroll
        for (int nt = 0; nt < 4; nt++) {
            const int row = bm + warp_m + mt * 16 + (lane >> 2);
            const int col = bn + warp_n + nt * 8 + (lane & 3) * 2;
            *reinterpret_cast<float2*>(&C[(size_t)row * N + col]) =
                make_float2(acc[mt][nt][0], acc[mt][nt][1]);
            *reinterpret_cast<float2*>(&C[(size_t)(row + 8) * N + col]) =
                make_float2(acc[mt][nt][2], acc[mt][nt][3]);
        }
    }
}

// ---------------- RoPE (interleaved pairs, pos = s within sequence) ----------
__global__ void rope_kernel(float* __restrict__ t, const float* __restrict__ fc,
                            const float* __restrict__ fs, int nheads, int total) {
    int idx = blockIdx.x * blockDim.x + threadIdx.x;
    if (idx >= total) return;
    int i = idx & 63;                          // pair index within head
    int s = (idx / (64 * nheads)) & (SEQ - 1); // sequence position
    float c  = fc[s * 64 + i];
    float sn = fs[s * 64 + i];
    float2* p = reinterpret_cast<float2*>(t);
    float2 v = p[idx];
    p[idx] = make_float2(v.x * c - v.y * sn, v.x * sn + v.y * c);
}

// ---------------- causal flash attention (fp32, GQA 4:1) ---------------------
#define FB 64            // Br = Bc = 64
#define LT 132           // padded tile row stride (floats)
#define LS 68            // padded score row stride
#define FA_SMEM ((4 * FB * LT + FB * LS + 3 * FB + 4 * FB) * 4)

__global__ __launch_bounds__(256) void flash_kernel(const float* __restrict__ q,
                                                    const float* __restrict__ k,
                                                    const float* __restrict__ v,
                                                    float* __restrict__ o) {
    extern __shared__ float smf[];
    float* Qs = smf;
    float* Ks = Qs + FB * LT;
    float* Vs = Ks + FB * LT;
    float* Os = Vs + FB * LT;
    float* Ss = Os + FB * LT;
    float* mrow = Ss + FB * LS;
    float* lrow = mrow + FB;
    float* arow = lrow + FB;
    float* red  = arow + FB;   // [row*4 + quarter]

    const int tid = threadIdx.x;
    const int qt  = gridDim.x - 1 - blockIdx.x;  // heavy (later) tiles first
    const int h   = blockIdx.y;
    const int b   = blockIdx.z;
    const int kvh = h >> 2;                       // N_REP = 4

    // load Q tile [64 x 128]
    for (int i = tid; i < FB * 32; i += 256) {
        int r  = i >> 5;
        int d4 = (i & 31) << 2;
        int s  = qt * FB + r;
        float4 val = *reinterpret_cast<const float4*>(
            &q[(((size_t)b * SEQ + s) * NH + h) * HD + d4]);
        *reinterpret_cast<float4*>(&Qs[r * LT + d4]) = val;
    }
    for (int i = tid; i < FB * LT; i += 256) Os[i] = 0.f;
    if (tid < FB) { mrow[tid] = -INFINITY; lrow[tid] = 0.f; }
    __syncthreads();

    const int tx = tid & 15, ty = tid >> 4;
    const int row = tid & 63, quarter = tid >> 6;
    const float sc = 0.08838834764831845f;   // 1/sqrt(128)

    for (int kt = 0; kt <= qt; kt++) {
        // load K, V tiles
        for (int i = tid; i < FB * 32; i += 256) {
            int r  = i >> 5;
            int d4 = (i & 31) << 2;
            int s  = kt * FB + r;
            size_t base = (((size_t)b * SEQ + s) * NKV + kvh) * HD + d4;
            *reinterpret_cast<float4*>(&Ks[r * LT + d4]) =
                *reinterpret_cast<const float4*>(&k[base]);
            *reinterpret_cast<float4*>(&Vs[r * LT + d4]) =
                *reinterpret_cast<const float4*>(&v[base]);
        }
        __syncthreads();

        // S = Q K^T  (64x64, each thread 4x4)
        float acc[4][4];
#pragma unroll
        for (int i = 0; i < 4; i++)
#pragma unroll
            for (int j = 0; j < 4; j++) acc[i][j] = 0.f;

        for (int kk = 0; kk < HD; kk += 4) {
            float4 qv[4], kv4[4];
#pragma unroll
            for (int i = 0; i < 4; i++)
                qv[i] = *reinterpret_cast<const float4*>(&Qs[(ty * 4 + i) * LT + kk]);
#pragma unroll
            for (int j = 0; j < 4; j++)
                kv4[j] = *reinterpret_cast<const float4*>(&Ks[(tx * 4 + j) * LT + kk]);
#pragma unroll
            for (int i = 0; i < 4; i++)
#pragma unroll
                for (int j = 0; j < 4; j++)
                    acc[i][j] += qv[i].x * kv4[j].x + qv[i].y * kv4[j].y +
                                 qv[i].z * kv4[j].z + qv[i].w * kv4[j].w;
        }
#pragma unroll
        for (int i = 0; i < 4; i++)
#pragma unroll
            for (int j = 0; j < 4; j++) {
                int r = ty * 4 + i, c = tx * 4 + j;
                float sv = acc[i][j] * sc;
                if (kt == qt && c > r) sv = -INFINITY;
                Ss[r * LS + c] = sv;
            }
        __syncthreads();

        // online softmax: partial row max
        float pm = -INFINITY;
#pragma unroll
        for (int c = 0; c < 16; c++)
            pm = fmaxf(pm, Ss[row * LS + quarter * 16 + c]);
        red[row * 4 + quarter] = pm;
        __syncthreads();
        if (tid < FB) {
            float mo = mrow[tid];
            float mn = fmaxf(fmaxf(red[tid * 4 + 0], red[tid * 4 + 1]),
                             fmaxf(red[tid * 4 + 2], red[tid * 4 + 3]));
            mn = fmaxf(mo, mn);
            mrow[tid] = mn;
            arow[tid] = __expf(mo - mn);
        }
        __syncthreads();

        // exponentiate + partial sums
        float mn = mrow[row];
        float psum = 0.f;
#pragma unroll
        for (int c = 0; c < 16; c++) {
            float e = __expf(Ss[row * LS + quarter * 16 + c] - mn);
            Ss[row * LS + quarter * 16 + c] = e;
            psum += e;
        }
        red[row * 4 + quarter] = psum;
        __syncthreads();
        if (tid < FB)
            lrow[tid] = lrow[tid] * arow[tid] +
                        red[tid * 4 + 0] + red[tid * 4 + 1] +
                        red[tid * 4 + 2] + red[tid * 4 + 3];

        // O = O*alpha + P @ V   (each thread 4 rows x 8 cols)
        float oacc[4][8];
#pragma unroll
        for (int i = 0; i < 4; i++) {
            float al = arow[ty * 4 + i];
            float4 o0 = *reinterpret_cast<const float4*>(&Os[(ty * 4 + i) * LT + tx * 8]);
            float4 o1 = *reinterpret_cast<const float4*>(&Os[(ty * 4 + i) * LT + tx * 8 + 4]);
            oacc[i][0] = o0.x * al; oacc[i][1] = o0.y * al;
            oacc[i][2] = o0.z * al; oacc[i][3] = o0.w * al;
            oacc[i][4] = o1.x * al; oacc[i][5] = o1.y * al;
            oacc[i][6] = o1.z * al; oacc[i][7] = o1.w * al;
        }
        for (int kk = 0; kk < FB; kk++) {
            float4 v0 = *reinterpret_cast<const float4*>(&Vs[kk * LT + tx * 8]);
            float4 v1 = *reinterpret_cast<const float4*>(&Vs[kk * LT + tx * 8 + 4]);
#pragma unroll
            for (int i = 0; i < 4; i++) {
                float p = Ss[(ty * 4 + i) * LS + kk];
                oacc[i][0] = fmaf(p, v0.x, oacc[i][0]);
                oacc[i][1] = fmaf(p, v0.y, oacc[i][1]);
                oacc[i][2] = fmaf(p, v0.z, oacc[i][2]);
                oacc[i][3] = fmaf(p, v0.w, oacc[i][3]);
                oacc[i][4] = fmaf(p, v1.x, oacc[i][4]);
                oacc[i][5] = fmaf(p, v1.y, oacc[i][5]);
                oacc[i][6] = fmaf(p, v1.z, oacc[i][6]);
                oacc[i][7] = fmaf(p, v1.w, oacc[i][7]);
            }
        }
#pragma unroll
        for (int i = 0; i < 4; i++) {
            *reinterpret_cast<float4*>(&Os[(ty * 4 + i) * LT + tx * 8]) =
                make_float4(oacc[i][0], oacc[i][1], oacc[i][2], oacc[i][3]);
            *reinterpret_cast<float4*>(&Os[(ty * 4 + i) * LT + tx * 8 + 4]) =
                make_float4(oacc[i][4], oacc[i][5], oacc[i][6], oacc[i][7]);
        }
        __syncthreads();
    }

    // epilogue: O /= l, write to attn buffer [B,S,H,hd]
    for (int i = tid; i < FB * 32; i += 256) {
        int r  = i >> 5;
        int d4 = (i & 31) << 2;
        float inv = 1.f / lrow[r];
        float4 ov = *reinterpret_cast<const float4*>(&Os[r * LT + d4]);
        ov.x *= inv; ov.y *= inv; ov.z *= inv; ov.w *= inv;
        int s = qt * FB + r;
        *reinterpret_cast<float4*>(
            &o[(((size_t)b * SEQ + s) * NH + h) * HD + d4]) = ov;
    }
}

// ---------------- launch ------------------------------------------------------
extern "C" void kernel_launch(void* const* d_in, const int* in_sizes, int n_in,
                              void* d_out, int out_size) {
    const float* x  = (const float*)d_in[0];
    const float* wq = (const float*)d_in[1];
    const float* wk = (const float*)d_in[2];
    const float* wv = (const float*)d_in[3];
    const float* wo = (const float*)d_in[4];
    const float* fc = (const float*)d_in[5];
    const float* fs = (const float*)d_in[6];
    float* out = (float*)d_out;

    float *qp, *kp, *vp, *ap;
    cudaGetSymbolAddress((void**)&qp, g_q);
    cudaGetSymbolAddress((void**)&kp, g_k);
    cudaGetSymbolAddress((void**)&vp, g_v);
    cudaGetSymbolAddress((void**)&ap, g_attn);

    cudaFuncSetAttribute(flash_kernel, cudaFuncAttributeMaxDynamicSharedMemorySize,
                         FA_SMEM);

    // projections: out[M,N] = x[M,K] @ W[N,K]^T   (tf32 tensor cores)
    tf32_gemm_nt<<<dim3(DIMM / BN, MROWS / BM), 256>>>(x, wq, qp, MROWS, DIMM, DIMM);
    tf32_gemm_nt<<<dim3((NKV * HD) / BN, MROWS / BM), 256>>>(x, wk, kp, MROWS, NKV * HD, DIMM);
    tf32_gemm_nt<<<dim3((NKV * HD) / BN, MROWS / BM), 256>>>(x, wv, vp, MROWS, NKV * HD, DIMM);

    // RoPE
    {
        int totq = BATCH * SEQ * NH * (HD / 2);
        int totk = BATCH * SEQ * NKV * (HD / 2);
        rope_kernel<<<(totq + 255) / 256, 256>>>(qp, fc, fs, NH, totq);
        rope_kernel<<<(totk + 255) / 256, 256>>>(kp, fc, fs, NKV, totk);
    }

    // causal flash attention
    flash_kernel<<<dim3(SEQ / FB, NH, BATCH), 256, FA_SMEM>>>(qp, kp, vp, ap);

    // output projection (tf32 tensor cores)
    tf32_gemm_nt<<<dim3(DIMM / BN, MROWS / BM), 256>>>(ap, wo, out, MROWS, DIMM, DIMM);
}

// round 3
// speedup vs baseline: 3.2804x; 1.7990x over previous
#include <cuda_runtime.h>
#include <math.h>
#include <stdint.h>

#define BATCH 2
#define SEQ   2048
#define DIMM  4096
#define NH    32
#define NKV   8
#define HD    128
#define MROWS (BATCH * SEQ)   // 4096

// ---------------- scratch (static device globals; no allocation) -------------
__device__ float g_q[(size_t)MROWS * DIMM];            // 64 MB  [B,S,H,hd]
__device__ float g_k[(size_t)MROWS * NKV * HD];        // 16 MB  [B,S,KV,hd]
__device__ float g_v[(size_t)MROWS * NKV * HD];        // 16 MB
__device__ float g_attn[(size_t)MROWS * DIMM];         // 64 MB  [B,S,H,hd]

__device__ __forceinline__ uint32_t f2tf32(float x) {
    uint32_t u;
    asm("cvt.rna.tf32.f32 %0, %1;" : "=r"(u) : "f"(x));
    return u;
}

// ============================================================================
// tf32 tensor-core GEMM: C[M,N] = A[M,K] @ B[N,K]^T
// CTA tile 128x128x16, 8 warps (2x4), warp tile 64x32, mma.sync.m16n8k8.tf32
// ============================================================================
#define BM 128
#define BN 128
#define BK 16
#define SAST 20   // padded row stride (floats) for [row][k] tiles

__global__ __launch_bounds__(256, 2) void tf32_gemm_nt(const float* __restrict__ A,
                                                       const float* __restrict__ B,
                                                       float* __restrict__ C,
                                                       int M, int N, int K) {
    __shared__ float As[2][BM * SAST];
    __shared__ float Bs[2][BN * SAST];

    const int tid  = threadIdx.x;
    const int lane = tid & 31;
    const int wid  = tid >> 5;
    const int bm = blockIdx.y * BM;
    const int bn = blockIdx.x * BN;
    const int warp_m = (wid & 1) * 64;
    const int warp_n = (wid >> 1) * 32;

    const int r0 = tid >> 2;
    const int c0 = (tid & 3) << 2;
    const int r1 = r0 + 64;

    const float* Ag0 = A + (size_t)(bm + r0) * K + c0;
    const float* Ag1 = A + (size_t)(bm + r1) * K + c0;
    const float* Bg0 = B + (size_t)(bn + r0) * K + c0;
    const float* Bg1 = B + (size_t)(bn + r1) * K + c0;

    float acc[4][4][4];
#pragma unroll
    for (int i = 0; i < 4; i++)
#pragma unroll
        for (int j = 0; j < 4; j++)
#pragma unroll
            for (int c = 0; c < 4; c++) acc[i][j][c] = 0.f;

    {
        float4 va0 = *reinterpret_cast<const float4*>(Ag0);
        float4 va1 = *reinterpret_cast<const float4*>(Ag1);
        float4 vb0 = *reinterpret_cast<const float4*>(Bg0);
        float4 vb1 = *reinterpret_cast<const float4*>(Bg1);
        uint32_t* pa0 = reinterpret_cast<uint32_t*>(&As[0][r0 * SAST + c0]);
        uint32_t* pa1 = reinterpret_cast<uint32_t*>(&As[0][r1 * SAST + c0]);
        uint32_t* pb0 = reinterpret_cast<uint32_t*>(&Bs[0][r0 * SAST + c0]);
        uint32_t* pb1 = reinterpret_cast<uint32_t*>(&Bs[0][r1 * SAST + c0]);
        pa0[0]=f2tf32(va0.x); pa0[1]=f2tf32(va0.y); pa0[2]=f2tf32(va0.z); pa0[3]=f2tf32(va0.w);
        pa1[0]=f2tf32(va1.x); pa1[1]=f2tf32(va1.y); pa1[2]=f2tf32(va1.z); pa1[3]=f2tf32(va1.w);
        pb0[0]=f2tf32(vb0.x); pb0[1]=f2tf32(vb0.y); pb0[2]=f2tf32(vb0.z); pb0[3]=f2tf32(vb0.w);
        pb1[0]=f2tf32(vb1.x); pb1[1]=f2tf32(vb1.y); pb1[2]=f2tf32(vb1.z); pb1[3]=f2tf32(vb1.w);
    }
    __syncthreads();

    int buf = 0;
    for (int k0 = 0; k0 < K; k0 += BK) {
        float4 va0, va1, vb0, vb1;
        const bool more = (k0 + BK) < K;
        if (more) {
            va0 = *reinterpret_cast<const float4*>(Ag0 + k0 + BK);
            va1 = *reinterpret_cast<const float4*>(Ag1 + k0 + BK);
            vb0 = *reinterpret_cast<const float4*>(Bg0 + k0 + BK);
            vb1 = *reinterpret_cast<const float4*>(Bg1 + k0 + BK);
        }

        const float* sA = &As[buf][0];
        const float* sB = &Bs[buf][0];
#pragma unroll
        for (int kk = 0; kk < BK; kk += 8) {
            uint32_t afr[4][4];
            uint32_t bfr[4][2];
#pragma unroll
            for (int mt = 0; mt < 4; mt++) {
                const int mrow = warp_m + mt * 16 + (lane >> 2);
                const int kc   = kk + (lane & 3);
                afr[mt][0] = reinterpret_cast<const uint32_t*>(sA)[mrow * SAST + kc];
                afr[mt][1] = reinterpret_cast<const uint32_t*>(sA)[(mrow + 8) * SAST + kc];
                afr[mt][2] = reinterpret_cast<const uint32_t*>(sA)[mrow * SAST + kc + 4];
                afr[mt][3] = reinterpret_cast<const uint32_t*>(sA)[(mrow + 8) * SAST + kc + 4];
            }
#pragma unroll
            for (int nt = 0; nt < 4; nt++) {
                const int nrow = warp_n + nt * 8 + (lane >> 2);
                const int kc   = kk + (lane & 3);
                bfr[nt][0] = reinterpret_cast<const uint32_t*>(sB)[nrow * SAST + kc];
                bfr[nt][1] = reinterpret_cast<const uint32_t*>(sB)[nrow * SAST + kc + 4];
            }
#pragma unroll
            for (int mt = 0; mt < 4; mt++)
#pragma unroll
                for (int nt = 0; nt < 4; nt++) {
                    asm volatile(
                        "mma.sync.aligned.m16n8k8.row.col.f32.tf32.tf32.f32 "
                        "{%0,%1,%2,%3},{%4,%5,%6,%7},{%8,%9},{%0,%1,%2,%3};"
                        : "+f"(acc[mt][nt][0]), "+f"(acc[mt][nt][1]),
                          "+f"(acc[mt][nt][2]), "+f"(acc[mt][nt][3])
                        : "r"(afr[mt][0]), "r"(afr[mt][1]),
                          "r"(afr[mt][2]), "r"(afr[mt][3]),
                          "r"(bfr[nt][0]), "r"(bfr[nt][1]));
                }
        }

        if (more) {
            const int nb = buf ^ 1;
            uint32_t* pa0 = reinterpret_cast<uint32_t*>(&As[nb][r0 * SAST + c0]);
            uint32_t* pa1 = reinterpret_cast<uint32_t*>(&As[nb][r1 * SAST + c0]);
            uint32_t* pb0 = reinterpret_cast<uint32_t*>(&Bs[nb][r0 * SAST + c0]);
            uint32_t* pb1 = reinterpret_cast<uint32_t*>(&Bs[nb][r1 * SAST + c0]);
            pa0[0]=f2tf32(va0.x); pa0[1]=f2tf32(va0.y); pa0[2]=f2tf32(va0.z); pa0[3]=f2tf32(va0.w);
            pa1[0]=f2tf32(va1.x); pa1[1]=f2tf32(va1.y); pa1[2]=f2tf32(va1.z); pa1[3]=f2tf32(va1.w);
            pb0[0]=f2tf32(vb0.x); pb0[1]=f2tf32(vb0.y); pb0[2]=f2tf32(vb0.z); pb0[3]=f2tf32(vb0.w);
            pb1[0]=f2tf32(vb1.x); pb1[1]=f2tf32(vb1.y); pb1[2]=f2tf32(vb1.z); pb1[3]=f2tf32(vb1.w);
            __syncthreads();
            buf = nb;
        }
    }

#pragma unroll
    for (int mt = 0; mt < 4; mt++) {
#pragma unroll
        for (int nt = 0; nt < 4; nt++) {
            const int row = bm + warp_m + mt * 16 + (lane >> 2);
            const int col = bn + warp_n + nt * 8 + (lane & 3) * 2;
            *reinterpret_cast<float2*>(&C[(size_t)row * N + col]) =
                make_float2(acc[mt][nt][0], acc[mt][nt][1]);
            *reinterpret_cast<float2*>(&C[(size_t)(row + 8) * N + col]) =
                make_float2(acc[mt][nt][2], acc[mt][nt][3]);
        }
    }
}

// ---------------- RoPE (interleaved pairs, pos = s within sequence) ----------
__global__ void rope_kernel(float* __restrict__ t, const float* __restrict__ fc,
                            const float* __restrict__ fs, int nheads, int total) {
    int idx = blockIdx.x * blockDim.x + threadIdx.x;
    if (idx >= total) return;
    int i = idx & 63;
    int s = (idx / (64 * nheads)) & (SEQ - 1);
    float c  = fc[s * 64 + i];
    float sn = fs[s * 64 + i];
    float2* p = reinterpret_cast<float2*>(t);
    float2 v = p[idx];
    p[idx] = make_float2(v.x * c - v.y * sn, v.x * sn + v.y * c);
}

// ============================================================================
// tf32 tensor-core causal flash attention (GQA 4:1)
// Br=128, Bc=64, 8 warps x 16-row warp tiles, hd=128
// ============================================================================
#define FBR 128
#define FBC 64
#define FLT_ (HD + 4)     // 132 stride for Q/K/V tiles
#define FPS  (FBC + 4)    // 68 stride for P tile
#define FA_SMEM ((FBR * FLT_ + 2 * FBC * FLT_ + FBR * FPS) * 4)

__global__ __launch_bounds__(256) void flash_tc_kernel(const float* __restrict__ q,
                                                       const float* __restrict__ k,
                                                       const float* __restrict__ v,
                                                       float* __restrict__ o) {
    extern __shared__ float smf[];
    uint32_t* Qs = reinterpret_cast<uint32_t*>(smf);                 // [FBR][FLT_]
    uint32_t* Ks = Qs + FBR * FLT_;                                   // [FBC][FLT_]
    uint32_t* Vs = Ks + FBC * FLT_;                                   // [FBC][FLT_]
    uint32_t* Ps = Vs + FBC * FLT_;                                   // [FBR][FPS]

    const int tid  = threadIdx.x;
    const int lane = tid & 31;
    const int wid  = tid >> 5;
    const int warp_m = wid * 16;

    const int qt = gridDim.x - 1 - blockIdx.x;   // heavy tiles first
    const int h  = blockIdx.y;
    const int b  = blockIdx.z;
    const int kvh = h >> 2;
    const int qbase = qt * FBR;

    // load Q tile [128 x 128] -> tf32 smem
    for (int i = tid; i < FBR * 32; i += 256) {
        int r  = i >> 5;
        int d4 = (i & 31) << 2;
        float4 val = *reinterpret_cast<const float4*>(
            &q[(((size_t)b * SEQ + qbase + r) * NH + h) * HD + d4]);
        uint32_t* p = &Qs[r * FLT_ + d4];
        p[0] = f2tf32(val.x); p[1] = f2tf32(val.y);
        p[2] = f2tf32(val.z); p[3] = f2tf32(val.w);
    }

    float oacc[16][4];
#pragma unroll
    for (int nt = 0; nt < 16; nt++)
#pragma unroll
        for (int c = 0; c < 4; c++) oacc[nt][c] = 0.f;

    float m0 = -INFINITY, m1 = -INFINITY, l0 = 0.f, l1 = 0.f;
    const float scl = 0.08838834764831845f * 1.44269504088896340736f; // 1/sqrt(hd)*log2e

    const int nkt = 2 * qt + 2;
    for (int kt = 0; kt < nkt; kt++) {
        const int kvbase = kt * FBC;
        __syncthreads();   // protect Ks/Vs from previous iteration's readers
        for (int i = tid; i < FBC * 32; i += 256) {
            int r  = i >> 5;
            int d4 = (i & 31) << 2;
            size_t base = (((size_t)b * SEQ + kvbase + r) * NKV + kvh) * HD + d4;
            float4 kv4 = *reinterpret_cast<const float4*>(&k[base]);
            float4 vv4 = *reinterpret_cast<const float4*>(&v[base]);
            uint32_t* pk = &Ks[r * FLT_ + d4];
            uint32_t* pv = &Vs[r * FLT_ + d4];
            pk[0] = f2tf32(kv4.x); pk[1] = f2tf32(kv4.y);
            pk[2] = f2tf32(kv4.z); pk[3] = f2tf32(kv4.w);
            pv[0] = f2tf32(vv4.x); pv[1] = f2tf32(vv4.y);
            pv[2] = f2tf32(vv4.z); pv[3] = f2tf32(vv4.w);
        }
        __syncthreads();

        // ---- S = Q K^T : 16 rows x 64 cols per warp -------------------------
        float sacc[8][4];
#pragma unroll
        for (int n = 0; n < 8; n++)
#pragma unroll
            for (int c = 0; c < 4; c++) sacc[n][c] = 0.f;

#pragma unroll
        for (int k8 = 0; k8 < HD / 8; k8++) {
            const int kc = k8 * 8 + (lane & 3);
            const int mrow = warp_m + (lane >> 2);
            uint32_t a0 = Qs[mrow * FLT_ + kc];
            uint32_t a1 = Qs[(mrow + 8) * FLT_ + kc];
            uint32_t a2 = Qs[mrow * FLT_ + kc + 4];
            uint32_t a3 = Qs[(mrow + 8) * FLT_ + kc + 4];
#pragma unroll
            for (int n = 0; n < 8; n++) {
                const int nrow = n * 8 + (lane >> 2);
                uint32_t b0 = Ks[nrow * FLT_ + kc];
                uint32_t b1 = Ks[nrow * FLT_ + kc + 4];
                asm volatile(
                    "mma.sync.aligned.m16n8k8.row.col.f32.tf32.tf32.f32 "
                    "{%0,%1,%2,%3},{%4,%5,%6,%7},{%8,%9},{%0,%1,%2,%3};"
                    : "+f"(sacc[n][0]), "+f"(sacc[n][1]),
                      "+f"(sacc[n][2]), "+f"(sacc[n][3])
                    : "r"(a0), "r"(a1), "r"(a2), "r"(a3), "r"(b0), "r"(b1));
            }
        }

        // ---- scale + causal mask -------------------------------------------
        const int gr0 = qbase + warp_m + (lane >> 2);
        const int gr1 = gr0 + 8;
        const bool need_mask = (kvbase + FBC - 1) > (qbase + warp_m);
#pragma unroll
        for (int n = 0; n < 8; n++) {
            const int gc = kvbase + n * 8 + (lane & 3) * 2;
            sacc[n][0] *= scl; sacc[n][1] *= scl;
            sacc[n][2] *= scl; sacc[n][3] *= scl;
            if (need_mask) {
                if (gc     > gr0) sacc[n][0] = -INFINITY;
                if (gc + 1 > gr0) sacc[n][1] = -INFINITY;
                if (gc     > gr1) sacc[n][2] = -INFINITY;
                if (gc + 1 > gr1) sacc[n][3] = -INFINITY;
            }
        }

        // ---- online softmax -------------------------------------------------
        float mx0 = -INFINITY, mx1 = -INFINITY;
#pragma unroll
        for (int n = 0; n < 8; n++) {
            mx0 = fmaxf(mx0, fmaxf(sacc[n][0], sacc[n][1]));
            mx1 = fmaxf(mx1, fmaxf(sacc[n][2], sacc[n][3]));
        }
        mx0 = fmaxf(mx0, __shfl_xor_sync(0xffffffffu, mx0, 1));
        mx0 = fmaxf(mx0, __shfl_xor_sync(0xffffffffu, mx0, 2));
        mx1 = fmaxf(mx1, __shfl_xor_sync(0xffffffffu, mx1, 1));
        mx1 = fmaxf(mx1, __shfl_xor_sync(0xffffffffu, mx1, 2));

        const float mn0 = fmaxf(m0, mx0);
        const float mn1 = fmaxf(m1, mx1);
        const float al0 = exp2f(m0 - mn0);
        const float al1 = exp2f(m1 - mn1);
        m0 = mn0; m1 = mn1;

        float sum0 = 0.f, sum1 = 0.f;
        const int prow0 = warp_m + (lane >> 2);
#pragma unroll
        for (int n = 0; n < 8; n++) {
            float p0 = exp2f(sacc[n][0] - m0);
            float p1 = exp2f(sacc[n][1] - m0);
            float p2 = exp2f(sacc[n][2] - m1);
            float p3 = exp2f(sacc[n][3] - m1);
            sum0 += p0 + p1;
            sum1 += p2 + p3;
            const int col = n * 8 + (lane & 3) * 2;
            Ps[prow0 * FPS + col]           = f2tf32(p0);
            Ps[prow0 * FPS + col + 1]       = f2tf32(p1);
            Ps[(prow0 + 8) * FPS + col]     = f2tf32(p2);
            Ps[(prow0 + 8) * FPS + col + 1] = f2tf32(p3);
        }
        sum0 += __shfl_xor_sync(0xffffffffu, sum0, 1);
        sum0 += __shfl_xor_sync(0xffffffffu, sum0, 2);
        sum1 += __shfl_xor_sync(0xffffffffu, sum1, 1);
        sum1 += __shfl_xor_sync(0xffffffffu, sum1, 2);
        l0 = l0 * al0 + sum0;
        l1 = l1 * al1 + sum1;

        // rescale O
#pragma unroll
        for (int nt = 0; nt < 16; nt++) {
            oacc[nt][0] *= al0; oacc[nt][1] *= al0;
            oacc[nt][2] *= al1; oacc[nt][3] *= al1;
        }

        __syncwarp();

        // ---- O += P @ V -----------------------------------------------------
#pragma unroll
        for (int k8 = 0; k8 < FBC / 8; k8++) {
            const int kc = k8 * 8 + (lane & 3);
            uint32_t a0 = Ps[prow0 * FPS + kc];
            uint32_t a1 = Ps[(prow0 + 8) * FPS + kc];
            uint32_t a2 = Ps[prow0 * FPS + kc + 4];
            uint32_t a3 = Ps[(prow0 + 8) * FPS + kc + 4];
#pragma unroll
            for (int nt = 0; nt < 16; nt++) {
                const int ncol = nt * 8 + (lane >> 2);
                uint32_t b0 = Vs[kc * FLT_ + ncol];
                uint32_t b1 = Vs[(kc + 4) * FLT_ + ncol];
                asm volatile(
                    "mma.sync.aligned.m16n8k8.row.col.f32.tf32.tf32.f32 "
                    "{%0,%1,%2,%3},{%4,%5,%6,%7},{%8,%9},{%0,%1,%2,%3};"
                    : "+f"(oacc[nt][0]), "+f"(oacc[nt][1]),
                      "+f"(oacc[nt][2]), "+f"(oacc[nt][3])
                    : "r"(a0), "r"(a1), "r"(a2), "r"(a3), "r"(b0), "r"(b1));
            }
        }
    }

    // ---- epilogue: O /= l, direct store ------------------------------------
    const float inv0 = 1.f / l0;
    const float inv1 = 1.f / l1;
    const int gr0 = qbase + warp_m + (lane >> 2);
    const int gr1 = gr0 + 8;
#pragma unroll
    for (int nt = 0; nt < 16; nt++) {
        const int col = nt * 8 + (lane & 3) * 2;
        *reinterpret_cast<float2*>(
            &o[(((size_t)b * SEQ + gr0) * NH + h) * HD + col]) =
            make_float2(oacc[nt][0] * inv0, oacc[nt][1] * inv0);
        *reinterpret_cast<float2*>(
            &o[(((size_t)b * SEQ + gr1) * NH + h) * HD + col]) =
            make_float2(oacc[nt][2] * inv1, oacc[nt][3] * inv1);
    }
}

// ---------------- launch ------------------------------------------------------
extern "C" void kernel_launch(void* const* d_in, const int* in_sizes, int n_in,
                              void* d_out, int out_size) {
    const float* x  = (const float*)d_in[0];
    const float* wq = (const float*)d_in[1];
    const float* wk = (const float*)d_in[2];
    const float* wv = (const float*)d_in[3];
    const float* wo = (const float*)d_in[4];
    const float* fc = (const float*)d_in[5];
    const float* fs = (const float*)d_in[6];
    float* out = (float*)d_out;

    float *qp, *kp, *vp, *ap;
    cudaGetSymbolAddress((void**)&qp, g_q);
    cudaGetSymbolAddress((void**)&kp, g_k);
    cudaGetSymbolAddress((void**)&vp, g_v);
    cudaGetSymbolAddress((void**)&ap, g_attn);

    cudaFuncSetAttribute(flash_tc_kernel, cudaFuncAttributeMaxDynamicSharedMemorySize,
                         FA_SMEM);

    // projections (tf32 tensor cores)
    tf32_gemm_nt<<<dim3(DIMM / BN, MROWS / BM), 256>>>(x, wq, qp, MROWS, DIMM, DIMM);
    tf32_gemm_nt<<<dim3((NKV * HD) / BN, MROWS / BM), 256>>>(x, wk, kp, MROWS, NKV * HD, DIMM);
    tf32_gemm_nt<<<dim3((NKV * HD) / BN, MROWS / BM), 256>>>(x, wv, vp, MROWS, NKV * HD, DIMM);

    // RoPE
    {
        int totq = BATCH * SEQ * NH * (HD / 2);
        int totk = BATCH * SEQ * NKV * (HD / 2);
        rope_kernel<<<(totq + 255) / 256, 256>>>(qp, fc, fs, NH, totq);
        rope_kernel<<<(totk + 255) / 256, 256>>>(kp, fc, fs, NKV, totk);
    }

    // causal flash attention (tf32 tensor cores)
    flash_tc_kernel<<<dim3(SEQ / FBR, NH, BATCH), 256, FA_SMEM>>>(qp, kp, vp, ap);

    // output projection (tf32 tensor cores)
    tf32_gemm_nt<<<dim3(DIMM / BN, MROWS / BM), 256>>>(ap, wo, out, MROWS, DIMM, DIMM);
}

// round 4
// speedup vs baseline: 3.2869x; 1.0020x over previous
#include <cuda_runtime.h>
#include <math.h>
#include <stdint.h>

#define BATCH 2
#define SEQ   2048
#define DIMM  4096
#define NH    32
#define NKV   8
#define HD    128
#define MROWS (BATCH * SEQ)   // 4096

// ---------------- scratch (static device globals; no allocation) -------------
__device__ float g_q[(size_t)MROWS * DIMM];            // 64 MB  [B,S,H,hd]
__device__ float g_k[(size_t)MROWS * NKV * HD];        // 16 MB  [B,S,KV,hd]
__device__ float g_v[(size_t)MROWS * NKV * HD];        // 16 MB
__device__ float g_attn[(size_t)MROWS * DIMM];         // 64 MB  [B,S,H,hd]

__device__ __forceinline__ uint32_t f2tf32(float x) {
    uint32_t u;
    asm("cvt.rna.tf32.f32 %0, %1;" : "=r"(u) : "f"(x));
    return u;
}

// ============================================================================
// tf32 tensor-core GEMM: C[M,N] = A[M,K] @ B[N,K]^T, optional fused RoPE
// CTA tile 128x128x16, 8 warps (2x4), warp tile 64x32, mma.sync.m16n8k8.tf32
// smem layout: [row][16] tf32, phys col = c ^ (8*((row>>1)&1))
//   -> LDS.64 fragments and STS.128 staging both bank-conflict-free.
// k-pairing: mma k-lane t holds logical cols (2t, 2t+1) in its (k, k+4) slots;
// valid because the k-sum order inside an 8-chunk is arbitrary (A and B agree).
// ============================================================================
#define BM 128
#define BN 128
#define BK 16

__global__ __launch_bounds__(256, 2) void tf32_gemm_nt(const float* __restrict__ A,
                                                       const float* __restrict__ B,
                                                       float* __restrict__ C,
                                                       int M, int N, int K,
                                                       const float* __restrict__ fc,
                                                       const float* __restrict__ fs) {
    __shared__ uint32_t As[2][BM * BK];
    __shared__ uint32_t Bs[2][BN * BK];

    const int tid  = threadIdx.x;
    const int lane = tid & 31;
    const int wid  = tid >> 5;
    const int bm = blockIdx.y * BM;
    const int bn = blockIdx.x * BN;
    const int warp_m = (wid & 1) * 64;
    const int warp_n = (wid >> 1) * 32;

    // staging: thread covers rows r0, r0+64, 4 logical cols starting at c0
    const int r0 = tid >> 2;
    const int r1 = r0 + 64;
    const int c0 = (tid & 3) << 2;
    const int sxor = ((tid >> 3) & 1) << 3;           // row-parity XOR (bit1 of row)
    const int sA0 = r0 * BK + (c0 ^ sxor);
    const int sA1 = r1 * BK + (c0 ^ sxor);            // (r0+64)>>1 has same bit0 parity

    const float* Ag0 = A + (size_t)(bm + r0) * K + c0;
    const float* Ag1 = A + (size_t)(bm + r1) * K + c0;
    const float* Bg0 = B + (size_t)(bn + r0) * K + c0;
    const float* Bg1 = B + (size_t)(bn + r1) * K + c0;

    float acc[4][4][4];
#pragma unroll
    for (int i = 0; i < 4; i++)
#pragma unroll
        for (int j = 0; j < 4; j++)
#pragma unroll
            for (int c = 0; c < 4; c++) acc[i][j][c] = 0.f;

    // prologue: tile 0 -> buf 0
    {
        float4 va0 = *reinterpret_cast<const float4*>(Ag0);
        float4 va1 = *reinterpret_cast<const float4*>(Ag1);
        float4 vb0 = *reinterpret_cast<const float4*>(Bg0);
        float4 vb1 = *reinterpret_cast<const float4*>(Bg1);
        *reinterpret_cast<uint4*>(&As[0][sA0]) =
            make_uint4(f2tf32(va0.x), f2tf32(va0.y), f2tf32(va0.z), f2tf32(va0.w));
        *reinterpret_cast<uint4*>(&As[0][sA1]) =
            make_uint4(f2tf32(va1.x), f2tf32(va1.y), f2tf32(va1.z), f2tf32(va1.w));
        *reinterpret_cast<uint4*>(&Bs[0][sA0]) =
            make_uint4(f2tf32(vb0.x), f2tf32(vb0.y), f2tf32(vb0.z), f2tf32(vb0.w));
        *reinterpret_cast<uint4*>(&Bs[0][sA1]) =
            make_uint4(f2tf32(vb1.x), f2tf32(vb1.y), f2tf32(vb1.z), f2tf32(vb1.w));
    }
    __syncthreads();

    // fragment addressing constants
    const int qa = lane >> 2;
    const int t2 = (lane & 3) * 2;
    const int xr = ((lane >> 3) & 1) << 3;            // (row>>1)&1 == (qa>>1)&1 for all tiles

    int buf = 0;
    for (int k0 = 0; k0 < K; k0 += BK) {
        float4 va0, va1, vb0, vb1;
        const bool more = (k0 + BK) < K;
        if (more) {
            va0 = *reinterpret_cast<const float4*>(Ag0 + k0 + BK);
            va1 = *reinterpret_cast<const float4*>(Ag1 + k0 + BK);
            vb0 = *reinterpret_cast<const float4*>(Bg0 + k0 + BK);
            vb1 = *reinterpret_cast<const float4*>(Bg1 + k0 + BK);
        }

        const uint32_t* sA = As[buf];
        const uint32_t* sB = Bs[buf];
#pragma unroll
        for (int kk = 0; kk < BK; kk += 8) {
            const int colk = (kk + t2) ^ xr;
            uint2 Af[4][2];
            uint2 Bf[4];
#pragma unroll
            for (int mt = 0; mt < 4; mt++) {
                const int mi = (warp_m + mt * 16 + qa) * BK + colk;
                Af[mt][0] = *reinterpret_cast<const uint2*>(&sA[mi]);
                Af[mt][1] = *reinterpret_cast<const uint2*>(&sA[mi + 8 * BK]);
            }
#pragma unroll
            for (int nt = 0; nt < 4; nt++) {
                const int ni = (warp_n + nt * 8 + qa) * BK + colk;
                Bf[nt] = *reinterpret_cast<const uint2*>(&sB[ni]);
            }
#pragma unroll
            for (int mt = 0; mt < 4; mt++)
#pragma unroll
                for (int nt = 0; nt < 4; nt++) {
                    asm volatile(
                        "mma.sync.aligned.m16n8k8.row.col.f32.tf32.tf32.f32 "
                        "{%0,%1,%2,%3},{%4,%5,%6,%7},{%8,%9},{%0,%1,%2,%3};"
                        : "+f"(acc[mt][nt][0]), "+f"(acc[mt][nt][1]),
                          "+f"(acc[mt][nt][2]), "+f"(acc[mt][nt][3])
                        : "r"(Af[mt][0].x), "r"(Af[mt][1].x),
                          "r"(Af[mt][0].y), "r"(Af[mt][1].y),
                          "r"(Bf[nt].x), "r"(Bf[nt].y));
                }
        }

        if (more) {
            const int nb = buf ^ 1;
            *reinterpret_cast<uint4*>(&As[nb][sA0]) =
                make_uint4(f2tf32(va0.x), f2tf32(va0.y), f2tf32(va0.z), f2tf32(va0.w));
            *reinterpret_cast<uint4*>(&As[nb][sA1]) =
                make_uint4(f2tf32(va1.x), f2tf32(va1.y), f2tf32(va1.z), f2tf32(va1.w));
            *reinterpret_cast<uint4*>(&Bs[nb][sA0]) =
                make_uint4(f2tf32(vb0.x), f2tf32(vb0.y), f2tf32(vb0.z), f2tf32(vb0.w));
            *reinterpret_cast<uint4*>(&Bs[nb][sA1]) =
                make_uint4(f2tf32(vb1.x), f2tf32(vb1.y), f2tf32(vb1.z), f2tf32(vb1.w));
            __syncthreads();
            buf = nb;
        }
    }

    // epilogue (optional fused RoPE: pairs are the even/odd float2 we write)
#pragma unroll
    for (int mt = 0; mt < 4; mt++) {
#pragma unroll
        for (int nt = 0; nt < 4; nt++) {
            const int row = bm + warp_m + mt * 16 + qa;
            const int col = bn + warp_n + nt * 8 + (lane & 3) * 2;
            float2 v0 = make_float2(acc[mt][nt][0], acc[mt][nt][1]);
            float2 v1 = make_float2(acc[mt][nt][2], acc[mt][nt][3]);
            if (fc) {
                const int i = (col & (HD - 1)) >> 1;
                const int s0 = row & (SEQ - 1);
                const int s1 = (row + 8) & (SEQ - 1);
                const float c_ = fc[s0 * (HD / 2) + i];
                const float n_ = fs[s0 * (HD / 2) + i];
                v0 = make_float2(v0.x * c_ - v0.y * n_, v0.x * n_ + v0.y * c_);
                const float c2 = fc[s1 * (HD / 2) + i];
                const float n2 = fs[s1 * (HD / 2) + i];
                v1 = make_float2(v1.x * c2 - v1.y * n2, v1.x * n2 + v1.y * c2);
            }
            *reinterpret_cast<float2*>(&C[(size_t)row * N + col]) = v0;
            *reinterpret_cast<float2*>(&C[(size_t)(row + 8) * N + col]) = v1;
        }
    }
}

// ============================================================================
// tf32 tensor-core causal flash attention (GQA 4:1)
// Br=128, Bc=64, 8 warps x 16-row warp tiles, hd=128
// ============================================================================
#define FBR 128
#define FBC 64
#define FLT_ (HD + 4)     // 132 stride for Q/K/V tiles
#define FPS  (FBC + 4)    // 68 stride for P tile
#define FA_SMEM ((FBR * FLT_ + 2 * FBC * FLT_ + FBR * FPS) * 4)

__global__ __launch_bounds__(256) void flash_tc_kernel(const float* __restrict__ q,
                                                       const float* __restrict__ k,
                                                       const float* __restrict__ v,
                                                       float* __restrict__ o) {
    extern __shared__ float smf[];
    uint32_t* Qs = reinterpret_cast<uint32_t*>(smf);
    uint32_t* Ks = Qs + FBR * FLT_;
    uint32_t* Vs = Ks + FBC * FLT_;
    uint32_t* Ps = Vs + FBC * FLT_;

    const int tid  = threadIdx.x;
    const int lane = tid & 31;
    const int wid  = tid >> 5;
    const int warp_m = wid * 16;

    const int qt = gridDim.x - 1 - blockIdx.x;
    const int h  = blockIdx.y;
    const int b  = blockIdx.z;
    const int kvh = h >> 2;
    const int qbase = qt * FBR;

    for (int i = tid; i < FBR * 32; i += 256) {
        int r  = i >> 5;
        int d4 = (i & 31) << 2;
        float4 val = *reinterpret_cast<const float4*>(
            &q[(((size_t)b * SEQ + qbase + r) * NH + h) * HD + d4]);
        uint32_t* p = &Qs[r * FLT_ + d4];
        p[0] = f2tf32(val.x); p[1] = f2tf32(val.y);
        p[2] = f2tf32(val.z); p[3] = f2tf32(val.w);
    }

    float oacc[16][4];
#pragma unroll
    for (int nt = 0; nt < 16; nt++)
#pragma unroll
        for (int c = 0; c < 4; c++) oacc[nt][c] = 0.f;

    float m0 = -INFINITY, m1 = -INFINITY, l0 = 0.f, l1 = 0.f;
    const float scl = 0.08838834764831845f * 1.44269504088896340736f;

    const int nkt = 2 * qt + 2;
    for (int kt = 0; kt < nkt; kt++) {
        const int kvbase = kt * FBC;
        __syncthreads();
        for (int i = tid; i < FBC * 32; i += 256) {
            int r  = i >> 5;
            int d4 = (i & 31) << 2;
            size_t base = (((size_t)b * SEQ + kvbase + r) * NKV + kvh) * HD + d4;
            float4 kv4 = *reinterpret_cast<const float4*>(&k[base]);
            float4 vv4 = *reinterpret_cast<const float4*>(&v[base]);
            uint32_t* pk = &Ks[r * FLT_ + d4];
            uint32_t* pv = &Vs[r * FLT_ + d4];
            pk[0] = f2tf32(kv4.x); pk[1] = f2tf32(kv4.y);
            pk[2] = f2tf32(kv4.z); pk[3] = f2tf32(kv4.w);
            pv[0] = f2tf32(vv4.x); pv[1] = f2tf32(vv4.y);
            pv[2] = f2tf32(vv4.z); pv[3] = f2tf32(vv4.w);
        }
        __syncthreads();

        float sacc[8][4];
#pragma unroll
        for (int n = 0; n < 8; n++)
#pragma unroll
            for (int c = 0; c < 4; c++) sacc[n][c] = 0.f;

#pragma unroll
        for (int k8 = 0; k8 < HD / 8; k8++) {
            const int kc = k8 * 8 + (lane & 3);
            const int mrow = warp_m + (lane >> 2);
            uint32_t a0 = Qs[mrow * FLT_ + kc];
            uint32_t a1 = Qs[(mrow + 8) * FLT_ + kc];
            uint32_t a2 = Qs[mrow * FLT_ + kc + 4];
            uint32_t a3 = Qs[(mrow + 8) * FLT_ + kc + 4];
#pragma unroll
            for (int n = 0; n < 8; n++) {
                const int nrow = n * 8 + (lane >> 2);
                uint32_t b0 = Ks[nrow * FLT_ + kc];
                uint32_t b1 = Ks[nrow * FLT_ + kc + 4];
                asm volatile(
                    "mma.sync.aligned.m16n8k8.row.col.f32.tf32.tf32.f32 "
                    "{%0,%1,%2,%3},{%4,%5,%6,%7},{%8,%9},{%0,%1,%2,%3};"
                    : "+f"(sacc[n][0]), "+f"(sacc[n][1]),
                      "+f"(sacc[n][2]), "+f"(sacc[n][3])
                    : "r"(a0), "r"(a1), "r"(a2), "r"(a3), "r"(b0), "r"(b1));
            }
        }

        const int gr0 = qbase + warp_m + (lane >> 2);
        const int gr1 = gr0 + 8;
        const bool need_mask = (kvbase + FBC - 1) > (qbase + warp_m);
#pragma unroll
        for (int n = 0; n < 8; n++) {
            const int gc = kvbase + n * 8 + (lane & 3) * 2;
            sacc[n][0] *= scl; sacc[n][1] *= scl;
            sacc[n][2] *= scl; sacc[n][3] *= scl;
            if (need_mask) {
                if (gc     > gr0) sacc[n][0] = -INFINITY;
                if (gc + 1 > gr0) sacc[n][1] = -INFINITY;
                if (gc     > gr1) sacc[n][2] = -INFINITY;
                if (gc + 1 > gr1) sacc[n][3] = -INFINITY;
            }
        }

        float mx0 = -INFINITY, mx1 = -INFINITY;
#pragma unroll
        for (int n = 0; n < 8; n++) {
            mx0 = fmaxf(mx0, fmaxf(sacc[n][0], sacc[n][1]));
            mx1 = fmaxf(mx1, fmaxf(sacc[n][2], sacc[n][3]));
        }
        mx0 = fmaxf(mx0, __shfl_xor_sync(0xffffffffu, mx0, 1));
        mx0 = fmaxf(mx0, __shfl_xor_sync(0xffffffffu, mx0, 2));
        mx1 = fmaxf(mx1, __shfl_xor_sync(0xffffffffu, mx1, 1));
        mx1 = fmaxf(mx1, __shfl_xor_sync(0xffffffffu, mx1, 2));

        const float mn0 = fmaxf(m0, mx0);
        const float mn1 = fmaxf(m1, mx1);
        const float al0 = exp2f(m0 - mn0);
        const float al1 = exp2f(m1 - mn1);
        m0 = mn0; m1 = mn1;

        float sum0 = 0.f, sum1 = 0.f;
        const int prow0 = warp_m + (lane >> 2);
#pragma unroll
        for (int n = 0; n < 8; n++) {
            float p0 = exp2f(sacc[n][0] - m0);
            float p1 = exp2f(sacc[n][1] - m0);
            float p2 = exp2f(sacc[n][2] - m1);
            float p3 = exp2f(sacc[n][3] - m1);
            sum0 += p0 + p1;
            sum1 += p2 + p3;
            const int col = n * 8 + (lane & 3) * 2;
            Ps[prow0 * FPS + col]           = f2tf32(p0);
            Ps[prow0 * FPS + col + 1]       = f2tf32(p1);
            Ps[(prow0 + 8) * FPS + col]     = f2tf32(p2);
            Ps[(prow0 + 8) * FPS + col + 1] = f2tf32(p3);
        }
        sum0 += __shfl_xor_sync(0xffffffffu, sum0, 1);
        sum0 += __shfl_xor_sync(0xffffffffu, sum0, 2);
        sum1 += __shfl_xor_sync(0xffffffffu, sum1, 1);
        sum1 += __shfl_xor_sync(0xffffffffu, sum1, 2);
        l0 = l0 * al0 + sum0;
        l1 = l1 * al1 + sum1;

#pragma unroll
        for (int nt = 0; nt < 16; nt++) {
            oacc[nt][0] *= al0; oacc[nt][1] *= al0;
            oacc[nt][2] *= al1; oacc[nt][3] *= al1;
        }

        __syncwarp();

#pragma unroll
        for (int k8 = 0; k8 < FBC / 8; k8++) {
            const int kc = k8 * 8 + (lane & 3);
            uint32_t a0 = Ps[prow0 * FPS + kc];
            uint32_t a1 = Ps[(prow0 + 8) * FPS + kc];
            uint32_t a2 = Ps[prow0 * FPS + kc + 4];
            uint32_t a3 = Ps[(prow0 + 8) * FPS + kc + 4];
#pragma unroll
            for (int nt = 0; nt < 16; nt++) {
                const int ncol = nt * 8 + (lane >> 2);
                uint32_t b0 = Vs[kc * FLT_ + ncol];
                uint32_t b1 = Vs[(kc + 4) * FLT_ + ncol];
                asm volatile(
                    "mma.sync.aligned.m16n8k8.row.col.f32.tf32.tf32.f32 "
                    "{%0,%1,%2,%3},{%4,%5,%6,%7},{%8,%9},{%0,%1,%2,%3};"
                    : "+f"(oacc[nt][0]), "+f"(oacc[nt][1]),
                      "+f"(oacc[nt][2]), "+f"(oacc[nt][3])
                    : "r"(a0), "r"(a1), "r"(a2), "r"(a3), "r"(b0), "r"(b1));
            }
        }
    }

    const float inv0 = 1.f / l0;
    const float inv1 = 1.f / l1;
    const int gr0 = qbase + warp_m + (lane >> 2);
    const int gr1 = gr0 + 8;
#pragma unroll
    for (int nt = 0; nt < 16; nt++) {
        const int col = nt * 8 + (lane & 3) * 2;
        *reinterpret_cast<float2*>(
            &o[(((size_t)b * SEQ + gr0) * NH + h) * HD + col]) =
            make_float2(oacc[nt][0] * inv0, oacc[nt][1] * inv0);
        *reinterpret_cast<float2*>(
            &o[(((size_t)b * SEQ + gr1) * NH + h) * HD + col]) =
            make_float2(oacc[nt][2] * inv1, oacc[nt][3] * inv1);
    }
}

// ---------------- launch ------------------------------------------------------
extern "C" void kernel_launch(void* const* d_in, const int* in_sizes, int n_in,
                              void* d_out, int out_size) {
    const float* x  = (const float*)d_in[0];
    const float* wq = (const float*)d_in[1];
    const float* wk = (const float*)d_in[2];
    const float* wv = (const float*)d_in[3];
    const float* wo = (const float*)d_in[4];
    const float* fc = (const float*)d_in[5];
    const float* fs = (const float*)d_in[6];
    float* out = (float*)d_out;

    float *qp, *kp, *vp, *ap;
    cudaGetSymbolAddress((void**)&qp, g_q);
    cudaGetSymbolAddress((void**)&kp, g_k);
    cudaGetSymbolAddress((void**)&vp, g_v);
    cudaGetSymbolAddress((void**)&ap, g_attn);

    cudaFuncSetAttribute(flash_tc_kernel, cudaFuncAttributeMaxDynamicSharedMemorySize,
                         FA_SMEM);

    // projections (tf32 tensor cores); RoPE fused into Q/K epilogues
    tf32_gemm_nt<<<dim3(DIMM / BN, MROWS / BM), 256>>>(x, wq, qp, MROWS, DIMM, DIMM, fc, fs);
    tf32_gemm_nt<<<dim3((NKV * HD) / BN, MROWS / BM), 256>>>(x, wk, kp, MROWS, NKV * HD, DIMM, fc, fs);
    tf32_gemm_nt<<<dim3((NKV * HD) / BN, MROWS / BM), 256>>>(x, wv, vp, MROWS, NKV * HD, DIMM, nullptr, nullptr);

    // causal flash attention (tf32 tensor cores)
    flash_tc_kernel<<<dim3(SEQ / FBR, NH, BATCH), 256, FA_SMEM>>>(qp, kp, vp, ap);

    // output projection
    tf32_gemm_nt<<<dim3(DIMM / BN, MROWS / BM), 256>>>(ap, wo, out, MROWS, DIMM, DIMM, nullptr, nullptr);
}

// round 5
// speedup vs baseline: 4.1776x; 1.2710x over previous
#include <cuda_runtime.h>
#include <cuda_fp16.h>
#include <math.h>
#include <stdint.h>

#define BATCH 2
#define SEQ   2048
#define DIMM  4096
#define NH    32
#define NKV   8
#define HD    128
#define MROWS (BATCH * SEQ)   // 4096

// ---------------- scratch (static device globals; no allocation) -------------
__device__ float g_q[(size_t)MROWS * DIMM];
__device__ float g_k[(size_t)MROWS * NKV * HD];
__device__ float g_v[(size_t)MROWS * NKV * HD];
__device__ float g_attn[(size_t)MROWS * DIMM];

__device__ __forceinline__ uint32_t f2h2(float a, float b) {
    __half2 h = __float22half2_rn(make_float2(a, b));
    return *reinterpret_cast<uint32_t*>(&h);
}

__device__ __forceinline__ void mma16816(float* d, const uint32_t* a,
                                         uint32_t b0, uint32_t b1) {
    asm volatile(
        "mma.sync.aligned.m16n8k16.row.col.f32.f16.f16.f32 "
        "{%0,%1,%2,%3},{%4,%5,%6,%7},{%8,%9},{%0,%1,%2,%3};"
        : "+f"(d[0]), "+f"(d[1]), "+f"(d[2]), "+f"(d[3])
        : "r"(a[0]), "r"(a[1]), "r"(a[2]), "r"(a[3]), "r"(b0), "r"(b1));
}

__device__ __forceinline__ void ldsm4(uint32_t* r, uint32_t addr) {
    asm volatile("ldmatrix.sync.aligned.m8n8.x4.shared.b16 {%0,%1,%2,%3}, [%4];"
                 : "=r"(r[0]), "=r"(r[1]), "=r"(r[2]), "=r"(r[3]) : "r"(addr));
}
__device__ __forceinline__ void ldsm4t(uint32_t* r, uint32_t addr) {
    asm volatile("ldmatrix.sync.aligned.m8n8.x4.trans.shared.b16 {%0,%1,%2,%3}, [%4];"
                 : "=r"(r[0]), "=r"(r[1]), "=r"(r[2]), "=r"(r[3]) : "r"(addr));
}

// ============================================================================
// fp16 tensor-core GEMM: C[M,N] = A[M,K] @ B[N,K]^T, optional fused RoPE
// CTA 128x128x32(halves), 8 warps (2x4), warp tile 64x32, mma.m16n8k16.f16
// smem: [row][32] halves, 16B chunk cc (0..3) at phys cc^(row&3).
// k-permutation: mma k-lane t holds logical k (4t..4t+3) in slots
// (a0a1, a4a5) -- valid since A and B use the same permutation.
// ============================================================================
#define BM 128
#define BN 128
#define BKH 32

__device__ __forceinline__ int gphys(int r, int c) {  // half index in tile
    return r * BKH + ((((c >> 3) ^ (r & 3)) << 3) | (c & 7));
}

__global__ __launch_bounds__(256, 2) void h16_gemm_nt(const float* __restrict__ A,
                                                      const float* __restrict__ B,
                                                      float* __restrict__ C,
                                                      int M, int N, int K,
                                                      const float* __restrict__ fc,
                                                      const float* __restrict__ fs) {
    __shared__ __half As[2][BM * BKH];
    __shared__ __half Bs[2][BN * BKH];

    const int tid  = threadIdx.x;
    const int lane = tid & 31;
    const int wid  = tid >> 5;
    const int bm = blockIdx.y * BM;
    const int bn = blockIdx.x * BN;
    const int warp_m = (wid & 1) * 64;
    const int warp_n = (wid >> 1) * 32;

    // staging: thread covers row r, halves c0..c0+15
    const int r0 = tid >> 1;
    const int c0 = (tid & 1) << 4;
    const int sw = r0 & 3;
    const int st0 = r0 * BKH + (((c0 >> 3) ^ sw) << 3);
    const int st1 = r0 * BKH + ((((c0 >> 3) + 1) ^ sw) << 3);

    const float* Ag = A + (size_t)(bm + r0) * K + c0;
    const float* Bg = B + (size_t)(bn + r0) * K + c0;

    float acc[4][4][4];
#pragma unroll
    for (int i = 0; i < 4; i++)
#pragma unroll
        for (int j = 0; j < 4; j++)
#pragma unroll
            for (int c = 0; c < 4; c++) acc[i][j][c] = 0.f;

    // prologue
    {
        float4 a0 = *reinterpret_cast<const float4*>(Ag);
        float4 a1 = *reinterpret_cast<const float4*>(Ag + 4);
        float4 a2 = *reinterpret_cast<const float4*>(Ag + 8);
        float4 a3 = *reinterpret_cast<const float4*>(Ag + 12);
        float4 b0 = *reinterpret_cast<const float4*>(Bg);
        float4 b1 = *reinterpret_cast<const float4*>(Bg + 4);
        float4 b2 = *reinterpret_cast<const float4*>(Bg + 8);
        float4 b3 = *reinterpret_cast<const float4*>(Bg + 12);
        *reinterpret_cast<uint4*>(&As[0][st0]) =
            make_uint4(f2h2(a0.x,a0.y), f2h2(a0.z,a0.w), f2h2(a1.x,a1.y), f2h2(a1.z,a1.w));
        *reinterpret_cast<uint4*>(&As[0][st1]) =
            make_uint4(f2h2(a2.x,a2.y), f2h2(a2.z,a2.w), f2h2(a3.x,a3.y), f2h2(a3.z,a3.w));
        *reinterpret_cast<uint4*>(&Bs[0][st0]) =
            make_uint4(f2h2(b0.x,b0.y), f2h2(b0.z,b0.w), f2h2(b1.x,b1.y), f2h2(b1.z,b1.w));
        *reinterpret_cast<uint4*>(&Bs[0][st1]) =
            make_uint4(f2h2(b2.x,b2.y), f2h2(b2.z,b2.w), f2h2(b3.x,b3.y), f2h2(b3.z,b3.w));
    }
    __syncthreads();

    const int qa = lane >> 2;
    const int tq = (lane & 3) << 2;   // logical k offset within 16-chunk

    int buf = 0;
    for (int k0 = 0; k0 < K; k0 += BKH) {
        float4 a0, a1, a2, a3, b0, b1, b2, b3;
        const bool more = (k0 + BKH) < K;
        if (more) {
            a0 = *reinterpret_cast<const float4*>(Ag + k0 + BKH);
            a1 = *reinterpret_cast<const float4*>(Ag + k0 + BKH + 4);
            a2 = *reinterpret_cast<const float4*>(Ag + k0 + BKH + 8);
            a3 = *reinterpret_cast<const float4*>(Ag + k0 + BKH + 12);
            b0 = *reinterpret_cast<const float4*>(Bg + k0 + BKH);
            b1 = *reinterpret_cast<const float4*>(Bg + k0 + BKH + 4);
            b2 = *reinterpret_cast<const float4*>(Bg + k0 + BKH + 8);
            b3 = *reinterpret_cast<const float4*>(Bg + k0 + BKH + 12);
        }

        const __half* sA = As[buf];
        const __half* sB = Bs[buf];
#pragma unroll
        for (int kk = 0; kk < BKH; kk += 16) {
            uint2 Au[4], Av[4], Bw[4];
#pragma unroll
            for (int mt = 0; mt < 4; mt++) {
                const int rA = warp_m + mt * 16 + qa;
                Au[mt] = *reinterpret_cast<const uint2*>(&sA[gphys(rA, kk + tq)]);
                Av[mt] = *reinterpret_cast<const uint2*>(&sA[gphys(rA + 8, kk + tq)]);
            }
#pragma unroll
            for (int nt = 0; nt < 4; nt++) {
                const int rB = warp_n + nt * 8 + qa;
                Bw[nt] = *reinterpret_cast<const uint2*>(&sB[gphys(rB, kk + tq)]);
            }
#pragma unroll
            for (int mt = 0; mt < 4; mt++) {
                uint32_t af[4] = {Au[mt].x, Av[mt].x, Au[mt].y, Av[mt].y};
#pragma unroll
                for (int nt = 0; nt < 4; nt++)
                    mma16816(acc[mt][nt], af, Bw[nt].x, Bw[nt].y);
            }
        }

        if (more) {
            const int nb = buf ^ 1;
            *reinterpret_cast<uint4*>(&As[nb][st0]) =
                make_uint4(f2h2(a0.x,a0.y), f2h2(a0.z,a0.w), f2h2(a1.x,a1.y), f2h2(a1.z,a1.w));
            *reinterpret_cast<uint4*>(&As[nb][st1]) =
                make_uint4(f2h2(a2.x,a2.y), f2h2(a2.z,a2.w), f2h2(a3.x,a3.y), f2h2(a3.z,a3.w));
            *reinterpret_cast<uint4*>(&Bs[nb][st0]) =
                make_uint4(f2h2(b0.x,b0.y), f2h2(b0.z,b0.w), f2h2(b1.x,b1.y), f2h2(b1.z,b1.w));
            *reinterpret_cast<uint4*>(&Bs[nb][st1]) =
                make_uint4(f2h2(b2.x,b2.y), f2h2(b2.z,b2.w), f2h2(b3.x,b3.y), f2h2(b3.z,b3.w));
            __syncthreads();
            buf = nb;
        }
    }

    // epilogue (optional fused RoPE)
#pragma unroll
    for (int mt = 0; mt < 4; mt++) {
#pragma unroll
        for (int nt = 0; nt < 4; nt++) {
            const int row = bm + warp_m + mt * 16 + qa;
            const int col = bn + warp_n + nt * 8 + (lane & 3) * 2;
            float2 v0 = make_float2(acc[mt][nt][0], acc[mt][nt][1]);
            float2 v1 = make_float2(acc[mt][nt][2], acc[mt][nt][3]);
            if (fc) {
                const int i = (col & (HD - 1)) >> 1;
                const int s0 = row & (SEQ - 1);
                const int s1 = (row + 8) & (SEQ - 1);
                const float c_ = fc[s0 * (HD / 2) + i];
                const float n_ = fs[s0 * (HD / 2) + i];
                v0 = make_float2(v0.x * c_ - v0.y * n_, v0.x * n_ + v0.y * c_);
                const float c2 = fc[s1 * (HD / 2) + i];
                const float n2 = fs[s1 * (HD / 2) + i];
                v1 = make_float2(v1.x * c2 - v1.y * n2, v1.x * n2 + v1.y * c2);
            }
            *reinterpret_cast<float2*>(&C[(size_t)row * N + col]) = v0;
            *reinterpret_cast<float2*>(&C[(size_t)(row + 8) * N + col]) = v1;
        }
    }
}

// ============================================================================
// fp16 tensor-core causal flash attention (GQA 4:1)
// Br=128, Bc=64, 8 warps x 16-row warp tiles, hd=128
// smem: Qh[128][128], Kh[64][128], Vh[64][128] halves,
// 16B chunk swizzle: phys chunk = chunk ^ (row & 7)  -> conflict-free ldmatrix
// P stays in registers (accumulator layout == next mma's A-fragment layout)
// ============================================================================
#define FBR 128
#define FBC 64
#define FA_SMEM ((FBR * HD + 2 * FBC * HD) * 2)

__global__ __launch_bounds__(256, 2) void flash_h_kernel(const float* __restrict__ q,
                                                         const float* __restrict__ k,
                                                         const float* __restrict__ v,
                                                         float* __restrict__ o) {
    extern __shared__ __half smh[];
    __half* Qh = smh;
    __half* Kh = Qh + FBR * HD;
    __half* Vh = Kh + FBC * HD;
    const uint32_t qsb = (uint32_t)__cvta_generic_to_shared(Qh);
    const uint32_t ksb = (uint32_t)__cvta_generic_to_shared(Kh);
    const uint32_t vsb = (uint32_t)__cvta_generic_to_shared(Vh);

    const int tid  = threadIdx.x;
    const int lane = tid & 31;
    const int wid  = tid >> 5;
    const int wm   = wid * 16;

    const int qt = gridDim.x - 1 - blockIdx.x;
    const int h  = blockIdx.y;
    const int b  = blockIdx.z;
    const int kvh = h >> 2;
    const int qbase = qt * FBR;

    // stage Q [128 rows][16 chunks]
    for (int i = tid; i < FBR * 16; i += 256) {
        const int row = i >> 4, ch = i & 15;
        const float* gp = &q[(((size_t)b * SEQ + qbase + row) * NH + h) * HD + ch * 8];
        float4 f0 = *reinterpret_cast<const float4*>(gp);
        float4 f1 = *reinterpret_cast<const float4*>(gp + 4);
        *reinterpret_cast<uint4*>(
            reinterpret_cast<char*>(Qh) + (((row << 4) + (ch ^ (row & 7))) << 4)) =
            make_uint4(f2h2(f0.x,f0.y), f2h2(f0.z,f0.w), f2h2(f1.x,f1.y), f2h2(f1.z,f1.w));
    }

    float oacc[16][4];
#pragma unroll
    for (int n = 0; n < 16; n++)
#pragma unroll
        for (int c = 0; c < 4; c++) oacc[n][c] = 0.f;

    float m0 = -INFINITY, m1 = -INFINITY, l0 = 0.f, l1 = 0.f;
    const float scl = 0.08838834764831845f * 1.44269504088896340736f;

    const int grp = lane >> 3, ls = lane & 7;
    const int nkt = 2 * qt + 2;
    for (int kt = 0; kt < nkt; kt++) {
        const int kvbase = kt * FBC;
        __syncthreads();
        for (int i = tid; i < FBC * 16; i += 256) {
            const int row = i >> 4, ch = i & 15;
            const size_t base = (((size_t)b * SEQ + kvbase + row) * NKV + kvh) * HD + ch * 8;
            float4 f0 = *reinterpret_cast<const float4*>(&k[base]);
            float4 f1 = *reinterpret_cast<const float4*>(&k[base + 4]);
            float4 g0 = *reinterpret_cast<const float4*>(&v[base]);
            float4 g1 = *reinterpret_cast<const float4*>(&v[base + 4]);
            const uint32_t off = ((row << 4) + (ch ^ (row & 7))) << 4;
            *reinterpret_cast<uint4*>(reinterpret_cast<char*>(Kh) + off) =
                make_uint4(f2h2(f0.x,f0.y), f2h2(f0.z,f0.w), f2h2(f1.x,f1.y), f2h2(f1.z,f1.w));
            *reinterpret_cast<uint4*>(reinterpret_cast<char*>(Vh) + off) =
                make_uint4(f2h2(g0.x,g0.y), f2h2(g0.z,g0.w), f2h2(g1.x,g1.y), f2h2(g1.z,g1.w));
        }
        __syncthreads();

        // ---- S = Q K^T ------------------------------------------------------
        float sacc[8][4];
#pragma unroll
        for (int n = 0; n < 8; n++)
#pragma unroll
            for (int c = 0; c < 4; c++) sacc[n][c] = 0.f;

#pragma unroll
        for (int i = 0; i < HD / 16; i++) {
            uint32_t qf[4], kf[4];
            const int qrow = wm + ls + ((grp & 1) << 3);
            const int qch  = 2 * i + (grp >> 1);
            ldsm4(qf, qsb + (((qrow << 4) + (qch ^ (qrow & 7))) << 4));
#pragma unroll
            for (int n0 = 0; n0 < 4; n0++) {
                const int krow = n0 * 16 + ls + ((grp >> 1) << 3);
                const int kch  = 2 * i + (grp & 1);
                ldsm4(kf, ksb + (((krow << 4) + (kch ^ (krow & 7))) << 4));
                mma16816(sacc[2 * n0],     qf, kf[0], kf[1]);
                mma16816(sacc[2 * n0 + 1], qf, kf[2], kf[3]);
            }
        }

        // ---- scale + causal mask -------------------------------------------
        const int gr0 = qbase + wm + (lane >> 2);
        const int gr1 = gr0 + 8;
        const bool need_mask = (kvbase + FBC - 1) > (qbase + wm);
#pragma unroll
        for (int n = 0; n < 8; n++) {
            const int gc = kvbase + n * 8 + (lane & 3) * 2;
            sacc[n][0] *= scl; sacc[n][1] *= scl;
            sacc[n][2] *= scl; sacc[n][3] *= scl;
            if (need_mask) {
                if (gc     > gr0) sacc[n][0] = -INFINITY;
                if (gc + 1 > gr0) sacc[n][1] = -INFINITY;
                if (gc     > gr1) sacc[n][2] = -INFINITY;
                if (gc + 1 > gr1) sacc[n][3] = -INFINITY;
            }
        }

        // ---- online softmax -------------------------------------------------
        float mx0 = -INFINITY, mx1 = -INFINITY;
#pragma unroll
        for (int n = 0; n < 8; n++) {
            mx0 = fmaxf(mx0, fmaxf(sacc[n][0], sacc[n][1]));
            mx1 = fmaxf(mx1, fmaxf(sacc[n][2], sacc[n][3]));
        }
        mx0 = fmaxf(mx0, __shfl_xor_sync(0xffffffffu, mx0, 1));
        mx0 = fmaxf(mx0, __shfl_xor_sync(0xffffffffu, mx0, 2));
        mx1 = fmaxf(mx1, __shfl_xor_sync(0xffffffffu, mx1, 1));
        mx1 = fmaxf(mx1, __shfl_xor_sync(0xffffffffu, mx1, 2));

        const float mn0 = fmaxf(m0, mx0);
        const float mn1 = fmaxf(m1, mx1);
        const float al0 = exp2f(m0 - mn0);
        const float al1 = exp2f(m1 - mn1);
        m0 = mn0; m1 = mn1;

        float sum0 = 0.f, sum1 = 0.f;
        uint32_t ph[8][2];
#pragma unroll
        for (int n = 0; n < 8; n++) {
            const float p0 = exp2f(sacc[n][0] - m0);
            const float p1 = exp2f(sacc[n][1] - m0);
            const float p2 = exp2f(sacc[n][2] - m1);
            const float p3 = exp2f(sacc[n][3] - m1);
            sum0 += p0 + p1;
            sum1 += p2 + p3;
            ph[n][0] = f2h2(p0, p1);
            ph[n][1] = f2h2(p2, p3);
        }
        sum0 += __shfl_xor_sync(0xffffffffu, sum0, 1);
        sum0 += __shfl_xor_sync(0xffffffffu, sum0, 2);
        sum1 += __shfl_xor_sync(0xffffffffu, sum1, 1);
        sum1 += __shfl_xor_sync(0xffffffffu, sum1, 2);
        l0 = l0 * al0 + sum0;
        l1 = l1 * al1 + sum1;

#pragma unroll
        for (int n = 0; n < 16; n++) {
            oacc[n][0] *= al0; oacc[n][1] *= al0;
            oacc[n][2] *= al1; oacc[n][3] *= al1;
        }

        // ---- O += P @ V  (P from registers, V via ldmatrix.trans) ----------
#pragma unroll
        for (int j = 0; j < FBC / 16; j++) {
            uint32_t pa[4] = {ph[2*j][0], ph[2*j][1], ph[2*j+1][0], ph[2*j+1][1]};
#pragma unroll
            for (int n0 = 0; n0 < HD / 16; n0++) {
                uint32_t vf[4];
                const int vrow = j * 16 + ls + ((grp & 1) << 3);
                const int vch  = 2 * n0 + (grp >> 1);
                ldsm4t(vf, vsb + (((vrow << 4) + (vch ^ (vrow & 7))) << 4));
                mma16816(oacc[2 * n0],     pa, vf[0], vf[1]);
                mma16816(oacc[2 * n0 + 1], pa, vf[2], vf[3]);
            }
        }
    }

    // ---- epilogue -----------------------------------------------------------
    const float inv0 = 1.f / l0;
    const float inv1 = 1.f / l1;
    const int gr0 = qbase + wm + (lane >> 2);
    const int gr1 = gr0 + 8;
#pragma unroll
    for (int n = 0; n < 16; n++) {
        const int col = n * 8 + (lane & 3) * 2;
        *reinterpret_cast<float2*>(
            &o[(((size_t)b * SEQ + gr0) * NH + h) * HD + col]) =
            make_float2(oacc[n][0] * inv0, oacc[n][1] * inv0);
        *reinterpret_cast<float2*>(
            &o[(((size_t)b * SEQ + gr1) * NH + h) * HD + col]) =
            make_float2(oacc[n][2] * inv1, oacc[n][3] * inv1);
    }
}

// ---------------- launch ------------------------------------------------------
extern "C" void kernel_launch(void* const* d_in, const int* in_sizes, int n_in,
                              void* d_out, int out_size) {
    const float* x  = (const float*)d_in[0];
    const float* wq = (const float*)d_in[1];
    const float* wk = (const float*)d_in[2];
    const float* wv = (const float*)d_in[3];
    const float* wo = (const float*)d_in[4];
    const float* fc = (const float*)d_in[5];
    const float* fs = (const float*)d_in[6];
    float* out = (float*)d_out;

    float *qp, *kp, *vp, *ap;
    cudaGetSymbolAddress((void**)&qp, g_q);
    cudaGetSymbolAddress((void**)&kp, g_k);
    cudaGetSymbolAddress((void**)&vp, g_v);
    cudaGetSymbolAddress((void**)&ap, g_attn);

    cudaFuncSetAttribute(flash_h_kernel, cudaFuncAttributeMaxDynamicSharedMemorySize,
                         FA_SMEM);

    // projections (fp16 tensor cores); RoPE fused into Q/K epilogues
    h16_gemm_nt<<<dim3(DIMM / BN, MROWS / BM), 256>>>(x, wq, qp, MROWS, DIMM, DIMM, fc, fs);
    h16_gemm_nt<<<dim3((NKV * HD) / BN, MROWS / BM), 256>>>(x, wk, kp, MROWS, NKV * HD, DIMM, fc, fs);
    h16_gemm_nt<<<dim3((NKV * HD) / BN, MROWS / BM), 256>>>(x, wv, vp, MROWS, NKV * HD, DIMM, nullptr, nullptr);

    // causal flash attention (fp16 tensor cores)
    flash_h_kernel<<<dim3(SEQ / FBR, NH, BATCH), 256, FA_SMEM>>>(qp, kp, vp, ap);

    // output projection
    h16_gemm_nt<<<dim3(DIMM / BN, MROWS / BM), 256>>>(ap, wo, out, MROWS, DIMM, DIMM, nullptr, nullptr);
}

// round 6
// speedup vs baseline: 8.3530x; 1.9995x over previous
#include <cuda_runtime.h>
#include <cuda_fp16.h>
#include <math.h>
#include <stdint.h>

#define BATCH 2
#define SEQ   2048
#define DIMM  4096
#define NH    32
#define NKV   8
#define HD    128
#define MROWS (BATCH * SEQ)          // 4096
#define KVD   (NKV * HD)             // 512
#define NQKV  (DIMM + 2 * KVD)       // 5120

// ---------------- fp16 scratch (static device globals) -----------------------
__device__ __half g_xh[(size_t)MROWS * DIMM];     // x in fp16
__device__ __half g_wh[(size_t)NQKV * DIMM];      // [wq;wk;wv] fp16
__device__ __half g_woh[(size_t)DIMM * DIMM];     // wo fp16
__device__ __half g_qh[(size_t)MROWS * DIMM];     // q (roped) fp16
__device__ __half g_kh[(size_t)MROWS * KVD];      // k (roped) fp16
__device__ __half g_vh[(size_t)MROWS * KVD];      // v fp16
__device__ __half g_ah[(size_t)MROWS * DIMM];     // attn out fp16

__device__ __forceinline__ uint32_t f2h2(float a, float b) {
    __half2 h = __float22half2_rn(make_float2(a, b));
    return *reinterpret_cast<uint32_t*>(&h);
}

__device__ __forceinline__ void mma16816(float* d, const uint32_t* a,
                                         uint32_t b0, uint32_t b1) {
    asm volatile(
        "mma.sync.aligned.m16n8k16.row.col.f32.f16.f16.f32 "
        "{%0,%1,%2,%3},{%4,%5,%6,%7},{%8,%9},{%0,%1,%2,%3};"
        : "+f"(d[0]), "+f"(d[1]), "+f"(d[2]), "+f"(d[3])
        : "r"(a[0]), "r"(a[1]), "r"(a[2]), "r"(a[3]), "r"(b0), "r"(b1));
}
__device__ __forceinline__ void ldsm4(uint32_t* r, uint32_t addr) {
    asm volatile("ldmatrix.sync.aligned.m8n8.x4.shared.b16 {%0,%1,%2,%3}, [%4];"
                 : "=r"(r[0]), "=r"(r[1]), "=r"(r[2]), "=r"(r[3]) : "r"(addr));
}
__device__ __forceinline__ void ldsm4t(uint32_t* r, uint32_t addr) {
    asm volatile("ldmatrix.sync.aligned.m8n8.x4.trans.shared.b16 {%0,%1,%2,%3}, [%4];"
                 : "=r"(r[0]), "=r"(r[1]), "=r"(r[2]), "=r"(r[3]) : "r"(addr));
}
__device__ __forceinline__ void cpa16(uint32_t dst, const void* src) {
    asm volatile("cp.async.cg.shared.global [%0], [%1], 16;" :: "r"(dst), "l"(src));
}
#define CP_COMMIT() asm volatile("cp.async.commit_group;")

// ---------------- fp32 -> fp16 convert (vectorized) --------------------------
__global__ void f2h_kernel(const float* __restrict__ in, __half* __restrict__ out,
                           int n8) {
    int i = blockIdx.x * blockDim.x + threadIdx.x;
    if (i >= n8) return;
    const float4* p = reinterpret_cast<const float4*>(in) + 2 * (size_t)i;
    float4 a = p[0], b = p[1];
    reinterpret_cast<uint4*>(out)[i] =
        make_uint4(f2h2(a.x, a.y), f2h2(a.z, a.w), f2h2(b.x, b.y), f2h2(b.z, b.w));
}

// ============================================================================
// fp16 GEMM, 3-stage cp.async pipeline: C = A[M,K] @ B[N,K]^T
// CTA 128x128x64(halves), 8 warps, warp tile 64x32.
// smem rows: 64 halves = 8 x 16B chunks, phys chunk = ch ^ (row & 7).
// mode 0: fp32 out Cf[row*4096+col]; mode 1: segmented fp16 out q/k/v + RoPE.
// ============================================================================
#define GBM 128
#define GBN 128
#define GBK 64
#define G_STAGE_BYTES ((GBM + GBN) * GBK * 2)     // 32768
#define G_SMEM (3 * G_STAGE_BYTES)                // 98304

__global__ __launch_bounds__(256, 2) void h16_gemm(
    const __half* __restrict__ A, const __half* __restrict__ B, int K,
    float* __restrict__ Cf,
    __half* __restrict__ qo, __half* __restrict__ ko, __half* __restrict__ vo,
    const float* __restrict__ fc, const float* __restrict__ fs, int mode) {
    extern __shared__ __half smh[];
    const uint32_t smb = (uint32_t)__cvta_generic_to_shared(smh);

    const int tid = threadIdx.x, lane = tid & 31, wid = tid >> 5;
    const int bm = blockIdx.y * GBM, bn = blockIdx.x * GBN;
    const int wm = (wid & 1) * 64, wn = (wid >> 1) * 32;

    // staging: thread -> row tid>>1, chunks (tid&1)*4 .. +3
    const int srow = tid >> 1;
    const int scb  = (tid & 1) * 4;
    const __half* Agp = A + (size_t)(bm + srow) * K + scb * 8;
    const __half* Bgp = B + (size_t)(bn + srow) * K + scb * 8;
    uint32_t adst[4], bdst[4];
#pragma unroll
    for (int c = 0; c < 4; c++) {
        const int sw = (scb + c) ^ (srow & 7);
        adst[c] = (uint32_t)((srow * 8 + sw) * 16);
        bdst[c] = adst[c] + (uint32_t)(GBM * GBK * 2);
    }

    float acc[4][4][4];
#pragma unroll
    for (int i = 0; i < 4; i++)
#pragma unroll
        for (int j = 0; j < 4; j++)
#pragma unroll
            for (int c = 0; c < 4; c++) acc[i][j][c] = 0.f;

    const int T = K / GBK;
    // prologue: stages 0,1
#pragma unroll
    for (int s = 0; s < 2; s++) {
        const uint32_t sb = smb + s * G_STAGE_BYTES;
#pragma unroll
        for (int c = 0; c < 4; c++) {
            cpa16(sb + adst[c], Agp + (size_t)s * GBK + c * 8);
            cpa16(sb + bdst[c], Bgp + (size_t)s * GBK + c * 8);
        }
        CP_COMMIT();
    }
    asm volatile("cp.async.wait_group 1;");
    __syncthreads();

    const int grp = lane >> 3, ls = lane & 7, qa = lane >> 2;

    int rs = 0;
    for (int t = 0; t < T; t++) {
        const int wt = t + 2;
        if (wt < T) {
            const int wsx = (rs + 2) % 3;
            const uint32_t sb = smb + wsx * G_STAGE_BYTES;
#pragma unroll
            for (int c = 0; c < 4; c++) {
                cpa16(sb + adst[c], Agp + (size_t)wt * GBK + c * 8);
                cpa16(sb + bdst[c], Bgp + (size_t)wt * GBK + c * 8);
            }
        }
        CP_COMMIT();

        const uint32_t Ab = smb + rs * G_STAGE_BYTES;
        const uint32_t Bb = Ab + (uint32_t)(GBM * GBK * 2);
#pragma unroll
        for (int kk = 0; kk < 4; kk++) {
            uint32_t af[4][4], bf[2][4];
#pragma unroll
            for (int mt = 0; mt < 4; mt++) {
                const int row = wm + mt * 16 + ls + ((grp & 1) << 3);
                const int ch  = 2 * kk + (grp >> 1);
                ldsm4(af[mt], Ab + ((row * 8 + (ch ^ (row & 7))) << 4));
            }
#pragma unroll
            for (int g = 0; g < 2; g++) {
                const int row = wn + g * 16 + ls + ((grp >> 1) << 3);
                const int ch  = 2 * kk + (grp & 1);
                ldsm4(bf[g], Bb + ((row * 8 + (ch ^ (row & 7))) << 4));
            }
#pragma unroll
            for (int mt = 0; mt < 4; mt++)
#pragma unroll
                for (int g = 0; g < 2; g++) {
                    mma16816(acc[mt][2 * g],     af[mt], bf[g][0], bf[g][1]);
                    mma16816(acc[mt][2 * g + 1], af[mt], bf[g][2], bf[g][3]);
                }
        }

        asm volatile("cp.async.wait_group 1;");
        __syncthreads();
        rs = (rs + 1) % 3;
    }

    // ---------------- epilogue ----------------
    if (mode == 0) {
#pragma unroll
        for (int mt = 0; mt < 4; mt++)
#pragma unroll
            for (int nt = 0; nt < 4; nt++) {
                const int row = bm + wm + mt * 16 + qa;
                const int col = bn + wn + nt * 8 + (lane & 3) * 2;
                *reinterpret_cast<float2*>(&Cf[(size_t)row * DIMM + col]) =
                    make_float2(acc[mt][nt][0], acc[mt][nt][1]);
                *reinterpret_cast<float2*>(&Cf[(size_t)(row + 8) * DIMM + col]) =
                    make_float2(acc[mt][nt][2], acc[mt][nt][3]);
            }
    } else {
        __half* outp; int colbase, stride; bool rope;
        if (bn < DIMM)            { outp = qo; colbase = bn;              stride = DIMM; rope = true; }
        else if (bn < DIMM + KVD) { outp = ko; colbase = bn - DIMM;       stride = KVD;  rope = true; }
        else                      { outp = vo; colbase = bn - DIMM - KVD; stride = KVD;  rope = false; }
#pragma unroll
        for (int mt = 0; mt < 4; mt++)
#pragma unroll
            for (int nt = 0; nt < 4; nt++) {
                const int row0 = bm + wm + mt * 16 + qa;
                const int row1 = row0 + 8;
                const int col  = colbase + wn + nt * 8 + (lane & 3) * 2;
                float2 v0 = make_float2(acc[mt][nt][0], acc[mt][nt][1]);
                float2 v1 = make_float2(acc[mt][nt][2], acc[mt][nt][3]);
                if (rope) {
                    const int i = (col & (HD - 1)) >> 1;
                    const float c0 = fc[(row0 & (SEQ - 1)) * (HD / 2) + i];
                    const float s0 = fs[(row0 & (SEQ - 1)) * (HD / 2) + i];
                    v0 = make_float2(v0.x * c0 - v0.y * s0, v0.x * s0 + v0.y * c0);
                    const float c1 = fc[(row1 & (SEQ - 1)) * (HD / 2) + i];
                    const float s1 = fs[(row1 & (SEQ - 1)) * (HD / 2) + i];
                    v1 = make_float2(v1.x * c1 - v1.y * s1, v1.x * s1 + v1.y * c1);
                }
                *reinterpret_cast<uint32_t*>(&outp[(size_t)row0 * stride + col]) = f2h2(v0.x, v0.y);
                *reinterpret_cast<uint32_t*>(&outp[(size_t)row1 * stride + col]) = f2h2(v1.x, v1.y);
            }
    }
}

// ============================================================================
// fp16 flash attention (GQA 4:1), cp.async double-buffered K/V
// Br=128, Bc=64, 8 warps x 16-row warp tiles, hd=128
// smem bytes: Q[0,32768) K0[32768) K1[49152) V0[65536) V1[81920) total 98304
// ============================================================================
#define FBR 128
#define FBC 64
#define FQB 0u
#define FKB 32768u
#define FVB 65536u
#define FKVSZ 16384u
#define F_SMEM 98304

__global__ __launch_bounds__(256, 2) void flash_h_kernel(const __half* __restrict__ q,
                                                         const __half* __restrict__ k,
                                                         const __half* __restrict__ v,
                                                         __half* __restrict__ o) {
    extern __shared__ __half smh[];
    const uint32_t smb = (uint32_t)__cvta_generic_to_shared(smh);

    const int tid  = threadIdx.x;
    const int lane = tid & 31;
    const int wid  = tid >> 5;
    const int wm   = wid * 16;

    const int qt = gridDim.x - 1 - blockIdx.x;
    const int h  = blockIdx.y;
    const int b  = blockIdx.z;
    const int kvh = h >> 2;
    const int qbase = qt * FBR;

    // Q staging coords: row tid>>1, chunks (tid&1)*8 .. +7   (16 chunks/row)
    {
        const int row = tid >> 1, cb = (tid & 1) * 8;
        const __half* src = &q[(((size_t)b * SEQ + qbase + row) * NH + h) * HD + cb * 8];
#pragma unroll
        for (int c = 0; c < 8; c++) {
            const int ch = cb + c;
            cpa16(smb + FQB + ((row * 16 + (ch ^ (row & 7))) << 4), src + c * 8);
        }
    }
    // KV staging coords: row tid>>2, chunks (tid&3)*4 .. +3
    const int kvrow = tid >> 2, kvcb = (tid & 3) * 4;
    uint32_t kvdst[4];
#pragma unroll
    for (int c = 0; c < 4; c++)
        kvdst[c] = (uint32_t)((kvrow * 16 + ((kvcb + c) ^ (kvrow & 7))) << 4);

    const int nkt = 2 * qt + 2;
    {
        const size_t base = (((size_t)b * SEQ + kvrow) * NKV + kvh) * HD + kvcb * 8;
#pragma unroll
        for (int c = 0; c < 4; c++) {
            cpa16(smb + FKB + kvdst[c], &k[base + c * 8]);
            cpa16(smb + FVB + kvdst[c], &v[base + c * 8]);
        }
    }
    CP_COMMIT();
    asm volatile("cp.async.wait_group 0;");
    __syncthreads();

    float oacc[16][4];
#pragma unroll
    for (int n = 0; n < 16; n++)
#pragma unroll
        for (int c = 0; c < 4; c++) oacc[n][c] = 0.f;

    float m0 = -INFINITY, m1 = -INFINITY, l0 = 0.f, l1 = 0.f;
    const float scl = 0.08838834764831845f * 1.44269504088896340736f;

    const int grp = lane >> 3, ls = lane & 7;

    for (int kt = 0; kt < nkt; kt++) {
        const int kvbase = kt * FBC;
        // prefetch next KV tile into other buffer
        if (kt + 1 < nkt) {
            const uint32_t ob = ((kt + 1) & 1) * FKVSZ;
            const size_t base =
                (((size_t)b * SEQ + (kt + 1) * FBC + kvrow) * NKV + kvh) * HD + kvcb * 8;
#pragma unroll
            for (int c = 0; c < 4; c++) {
                cpa16(smb + FKB + ob + kvdst[c], &k[base + c * 8]);
                cpa16(smb + FVB + ob + kvdst[c], &v[base + c * 8]);
            }
        }
        CP_COMMIT();

        const uint32_t ksb = smb + FKB + (kt & 1) * FKVSZ;
        const uint32_t vsb = smb + FVB + (kt & 1) * FKVSZ;
        const uint32_t qsb = smb + FQB;

        // ---- S = Q K^T ------------------------------------------------------
        float sacc[8][4];
#pragma unroll
        for (int n = 0; n < 8; n++)
#pragma unroll
            for (int c = 0; c < 4; c++) sacc[n][c] = 0.f;

#pragma unroll
        for (int i = 0; i < HD / 16; i++) {
            uint32_t qf[4], kf[4];
            const int qrow = wm + ls + ((grp & 1) << 3);
            const int qch  = 2 * i + (grp >> 1);
            ldsm4(qf, qsb + (((qrow << 4) + (qch ^ (qrow & 7))) << 4));
#pragma unroll
            for (int n0 = 0; n0 < 4; n0++) {
                const int krow = n0 * 16 + ls + ((grp >> 1) << 3);
                const int kch  = 2 * i + (grp & 1);
                ldsm4(kf, ksb + (((krow << 4) + (kch ^ (krow & 7))) << 4));
                mma16816(sacc[2 * n0],     qf, kf[0], kf[1]);
                mma16816(sacc[2 * n0 + 1], qf, kf[2], kf[3]);
            }
        }

        // ---- scale + causal mask -------------------------------------------
        const int gr0 = qbase + wm + (lane >> 2);
        const int gr1 = gr0 + 8;
        const bool need_mask = (kvbase + FBC - 1) > (qbase + wm);
#pragma unroll
        for (int n = 0; n < 8; n++) {
            const int gc = kvbase + n * 8 + (lane & 3) * 2;
            sacc[n][0] *= scl; sacc[n][1] *= scl;
            sacc[n][2] *= scl; sacc[n][3] *= scl;
            if (need_mask) {
                if (gc     > gr0) sacc[n][0] = -INFINITY;
                if (gc + 1 > gr0) sacc[n][1] = -INFINITY;
                if (gc     > gr1) sacc[n][2] = -INFINITY;
                if (gc + 1 > gr1) sacc[n][3] = -INFINITY;
            }
        }

        // ---- online softmax -------------------------------------------------
        float mx0 = -INFINITY, mx1 = -INFINITY;
#pragma unroll
        for (int n = 0; n < 8; n++) {
            mx0 = fmaxf(mx0, fmaxf(sacc[n][0], sacc[n][1]));
            mx1 = fmaxf(mx1, fmaxf(sacc[n][2], sacc[n][3]));
        }
        mx0 = fmaxf(mx0, __shfl_xor_sync(0xffffffffu, mx0, 1));
        mx0 = fmaxf(mx0, __shfl_xor_sync(0xffffffffu, mx0, 2));
        mx1 = fmaxf(mx1, __shfl_xor_sync(0xffffffffu, mx1, 1));
        mx1 = fmaxf(mx1, __shfl_xor_sync(0xffffffffu, mx1, 2));

        const float mn0 = fmaxf(m0, mx0);
        const float mn1 = fmaxf(m1, mx1);
        const float al0 = exp2f(m0 - mn0);
        const float al1 = exp2f(m1 - mn1);
        m0 = mn0; m1 = mn1;

        float sum0 = 0.f, sum1 = 0.f;
        uint32_t ph[8][2];
#pragma unroll
        for (int n = 0; n < 8; n++) {
            const float p0 = exp2f(sacc[n][0] - m0);
            const float p1 = exp2f(sacc[n][1] - m0);
            const float p2 = exp2f(sacc[n][2] - m1);
            const float p3 = exp2f(sacc[n][3] - m1);
            sum0 += p0 + p1;
            sum1 += p2 + p3;
            ph[n][0] = f2h2(p0, p1);
            ph[n][1] = f2h2(p2, p3);
        }
        sum0 += __shfl_xor_sync(0xffffffffu, sum0, 1);
        sum0 += __shfl_xor_sync(0xffffffffu, sum0, 2);
        sum1 += __shfl_xor_sync(0xffffffffu, sum1, 1);
        sum1 += __shfl_xor_sync(0xffffffffu, sum1, 2);
        l0 = l0 * al0 + sum0;
        l1 = l1 * al1 + sum1;

#pragma unroll
        for (int n = 0; n < 16; n++) {
            oacc[n][0] *= al0; oacc[n][1] *= al0;
            oacc[n][2] *= al1; oacc[n][3] *= al1;
        }

        // ---- O += P @ V -----------------------------------------------------
#pragma unroll
        for (int j = 0; j < FBC / 16; j++) {
            uint32_t pa[4] = {ph[2*j][0], ph[2*j][1], ph[2*j+1][0], ph[2*j+1][1]};
#pragma unroll
            for (int n0 = 0; n0 < HD / 16; n0++) {
                uint32_t vf[4];
                const int vrow = j * 16 + ls + ((grp & 1) << 3);
                const int vch  = 2 * n0 + (grp >> 1);
                ldsm4t(vf, vsb + (((vrow << 4) + (vch ^ (vrow & 7))) << 4));
                mma16816(oacc[2 * n0],     pa, vf[0], vf[1]);
                mma16816(oacc[2 * n0 + 1], pa, vf[2], vf[3]);
            }
        }

        asm volatile("cp.async.wait_group 0;");
        __syncthreads();
    }

    // ---- epilogue: write fp16 attn output -----------------------------------
    const float inv0 = 1.f / l0;
    const float inv1 = 1.f / l1;
    const int gr0 = qbase + wm + (lane >> 2);
    const int gr1 = gr0 + 8;
#pragma unroll
    for (int n = 0; n < 16; n++) {
        const int col = n * 8 + (lane & 3) * 2;
        *reinterpret_cast<uint32_t*>(
            &o[((size_t)b * SEQ + gr0) * DIMM + h * HD + col]) =
            f2h2(oacc[n][0] * inv0, oacc[n][1] * inv0);
        *reinterpret_cast<uint32_t*>(
            &o[((size_t)b * SEQ + gr1) * DIMM + h * HD + col]) =
            f2h2(oacc[n][2] * inv1, oacc[n][3] * inv1);
    }
}

// ---------------- launch ------------------------------------------------------
extern "C" void kernel_launch(void* const* d_in, const int* in_sizes, int n_in,
                              void* d_out, int out_size) {
    const float* x  = (const float*)d_in[0];
    const float* wq = (const float*)d_in[1];
    const float* wk = (const float*)d_in[2];
    const float* wv = (const float*)d_in[3];
    const float* wo = (const float*)d_in[4];
    const float* fc = (const float*)d_in[5];
    const float* fs = (const float*)d_in[6];
    float* out = (float*)d_out;

    __half *xh, *wh, *woh, *qh, *kh, *vh, *ah;
    cudaGetSymbolAddress((void**)&xh,  g_xh);
    cudaGetSymbolAddress((void**)&wh,  g_wh);
    cudaGetSymbolAddress((void**)&woh, g_woh);
    cudaGetSymbolAddress((void**)&qh,  g_qh);
    cudaGetSymbolAddress((void**)&kh,  g_kh);
    cudaGetSymbolAddress((void**)&vh,  g_vh);
    cudaGetSymbolAddress((void**)&ah,  g_ah);

    cudaFuncSetAttribute(h16_gemm, cudaFuncAttributeMaxDynamicSharedMemorySize, G_SMEM);
    cudaFuncSetAttribute(flash_h_kernel, cudaFuncAttributeMaxDynamicSharedMemorySize, F_SMEM);

    // fp32 -> fp16 converts
    {
        const int nx = MROWS * DIMM / 8;
        f2h_kernel<<<nx / 256, 256>>>(x, xh, nx);
        const int nq = DIMM * DIMM / 8;
        f2h_kernel<<<nq / 256, 256>>>(wq, wh, nq);
        const int nk = KVD * DIMM / 8;
        f2h_kernel<<<nk / 256, 256>>>(wk, wh + (size_t)DIMM * DIMM, nk);
        f2h_kernel<<<nk / 256, 256>>>(wv, wh + (size_t)(DIMM + KVD) * DIMM, nk);
        f2h_kernel<<<nq / 256, 256>>>(wo, woh, nq);
    }

    // fused QKV projection + RoPE (fp16 in, fp16 out)
    h16_gemm<<<dim3(NQKV / GBN, MROWS / GBM), 256, G_SMEM>>>(
        xh, wh, DIMM, nullptr, qh, kh, vh, fc, fs, 1);

    // causal flash attention (fp16)
    flash_h_kernel<<<dim3(SEQ / FBR, NH, BATCH), 256, F_SMEM>>>(qh, kh, vh, ah);

    // output projection (fp16 in, fp32 out)
    h16_gemm<<<dim3(DIMM / GBN, MROWS / GBM), 256, G_SMEM>>>(
        ah, woh, DIMM, out, nullptr, nullptr, nullptr, nullptr, nullptr, 0);
}